// round 4
// baseline (speedup 1.0000x reference)
#include <cuda_runtime.h>
#include <math.h>

#define HDIM 1024
#define NH 16
#define HD 64
#define BATCH 2
#define SEQ 2048
#define MROWS (BATCH*SEQ)   // 4096
#define LN_EPS 1e-5f

// Scratch (allocation-free rule: __device__ globals)
__device__ float g_xn[MROWS*HDIM];
__device__ float g_q [MROWS*HDIM];
__device__ float g_k [MROWS*HDIM];
__device__ float g_v [MROWS*HDIM];
__device__ float g_ao[MROWS*HDIM];

// ---------------------------------------------------------------------------
// LayerNorm: one block per row (1024 cols), 256 threads, float4 per thread.
// ---------------------------------------------------------------------------
__global__ void ln_kernel(const float* __restrict__ x,
                          const float* __restrict__ gamma,
                          const float* __restrict__ beta,
                          float* __restrict__ xn)
{
    int row = blockIdx.x;
    int tid = threadIdx.x;
    const float4* xr = (const float4*)(x + (size_t)row * HDIM);
    float4 v = xr[tid];
    float s  = v.x + v.y + v.z + v.w;
    float ss = v.x*v.x + v.y*v.y + v.z*v.z + v.w*v.w;
    #pragma unroll
    for (int o = 16; o; o >>= 1) {
        s  += __shfl_xor_sync(0xffffffffu, s,  o);
        ss += __shfl_xor_sync(0xffffffffu, ss, o);
    }
    __shared__ float red0[8], red1[8];
    int w = tid >> 5, l = tid & 31;
    if (l == 0) { red0[w] = s; red1[w] = ss; }
    __syncthreads();
    float ts = 0.f, tss = 0.f;
    #pragma unroll
    for (int i = 0; i < 8; i++) { ts += red0[i]; tss += red1[i]; }
    float mu  = ts * (1.0f / HDIM);
    float var = tss * (1.0f / HDIM) - mu * mu;
    float inv = rsqrtf(var + LN_EPS);

    float4 g = ((const float4*)gamma)[tid];
    float4 b = ((const float4*)beta)[tid];
    float4 o;
    o.x = (v.x - mu) * inv * g.x + b.x;
    o.y = (v.y - mu) * inv * g.y + b.y;
    o.z = (v.z - mu) * inv * g.z + b.z;
    o.w = (v.w - mu) * inv * g.w + b.w;
    ((float4*)(xn + (size_t)row * HDIM))[tid] = o;
}

// ---------------------------------------------------------------------------
// Tiled fp32 GEMM: C[M,N] = A[M,K] * W[N,K]^T  (both K-major), BM=BN=128, BK=16
// 256 threads, 8x8 micro-tile. gridDim.z selects (W,C) pair for fused QKV.
// EPI=1: C = A*W^T + bias + resid
// ---------------------------------------------------------------------------
template <int EPI>
__global__ void __launch_bounds__(256, 2)
gemm_nt(const float* __restrict__ A,
        const float* __restrict__ W0, const float* __restrict__ W1, const float* __restrict__ W2,
        float* __restrict__ C0, float* __restrict__ C1, float* __restrict__ C2,
        const float* __restrict__ bias, const float* __restrict__ resid)
{
    const int BM = 128, BN = 128, BK = 16;
    int z = blockIdx.z;
    const float* W = (z == 0) ? W0 : (z == 1 ? W1 : W2);
    float*       C = (z == 0) ? C0 : (z == 1 ? C1 : C2);

    __shared__ float As[BK][BM];
    __shared__ float Bs[BK][BN];

    int tid = threadIdx.x;
    int m0 = blockIdx.y * BM;
    int n0 = blockIdx.x * BN;
    int lr = tid >> 2;            // 0..63
    int lc = (tid & 3) << 2;      // 0,4,8,12
    int ty = tid >> 4;            // 0..15
    int tx = tid & 15;            // 0..15

    float acc[8][8];
    #pragma unroll
    for (int i = 0; i < 8; i++)
        #pragma unroll
        for (int j = 0; j < 8; j++) acc[i][j] = 0.f;

    const float* Ap = A + (size_t)(m0 + lr) * HDIM + lc;
    const float* Wp = W + (size_t)(n0 + lr) * HDIM + lc;

    for (int k0 = 0; k0 < HDIM; k0 += BK) {
        float4 a0 = *(const float4*)(Ap + k0);
        float4 a1 = *(const float4*)(Ap + (size_t)64 * HDIM + k0);
        float4 b0 = *(const float4*)(Wp + k0);
        float4 b1 = *(const float4*)(Wp + (size_t)64 * HDIM + k0);
        __syncthreads();
        As[lc+0][lr]    = a0.x; As[lc+1][lr]    = a0.y; As[lc+2][lr]    = a0.z; As[lc+3][lr]    = a0.w;
        As[lc+0][lr+64] = a1.x; As[lc+1][lr+64] = a1.y; As[lc+2][lr+64] = a1.z; As[lc+3][lr+64] = a1.w;
        Bs[lc+0][lr]    = b0.x; Bs[lc+1][lr]    = b0.y; Bs[lc+2][lr]    = b0.z; Bs[lc+3][lr]    = b0.w;
        Bs[lc+0][lr+64] = b1.x; Bs[lc+1][lr+64] = b1.y; Bs[lc+2][lr+64] = b1.z; Bs[lc+3][lr+64] = b1.w;
        __syncthreads();
        #pragma unroll
        for (int kk = 0; kk < BK; kk++) {
            float4 x0 = *(const float4*)&As[kk][ty*8];
            float4 x1 = *(const float4*)&As[kk][ty*8+4];
            float4 y0 = *(const float4*)&Bs[kk][tx*8];
            float4 y1 = *(const float4*)&Bs[kk][tx*8+4];
            float av[8] = {x0.x,x0.y,x0.z,x0.w,x1.x,x1.y,x1.z,x1.w};
            float bv[8] = {y0.x,y0.y,y0.z,y0.w,y1.x,y1.y,y1.z,y1.w};
            #pragma unroll
            for (int i = 0; i < 8; i++)
                #pragma unroll
                for (int j = 0; j < 8; j++)
                    acc[i][j] = fmaf(av[i], bv[j], acc[i][j]);
        }
    }

    float4 bi0 = make_float4(0,0,0,0), bi1 = make_float4(0,0,0,0);
    if (EPI) {
        bi0 = *(const float4*)(bias + n0 + tx*8);
        bi1 = *(const float4*)(bias + n0 + tx*8 + 4);
    }
    #pragma unroll
    for (int i = 0; i < 8; i++) {
        int row = m0 + ty*8 + i;
        float* Cp = C + (size_t)row * HDIM + n0 + tx*8;
        float4 o0 = make_float4(acc[i][0], acc[i][1], acc[i][2], acc[i][3]);
        float4 o1 = make_float4(acc[i][4], acc[i][5], acc[i][6], acc[i][7]);
        if (EPI) {
            const float* Rp = resid + (size_t)row * HDIM + n0 + tx*8;
            float4 r0 = *(const float4*)(Rp);
            float4 r1 = *(const float4*)(Rp + 4);
            o0.x += bi0.x + r0.x; o0.y += bi0.y + r0.y; o0.z += bi0.z + r0.z; o0.w += bi0.w + r0.w;
            o1.x += bi1.x + r1.x; o1.y += bi1.y + r1.y; o1.z += bi1.z + r1.z; o1.w += bi1.w + r1.w;
        }
        *(float4*)(Cp)     = o0;
        *(float4*)(Cp + 4) = o1;
    }
}

// ---------------------------------------------------------------------------
// Flash attention: BM=BN=64, HD=64, one block per (q-tile, b*h).
// 256 threads as 16x16; thread owns 4 q-rows x 4 cols.
// Smem: Qt[d][q], KP union (Kt[d][k] then Pt[k][q]), Vs[k][d] = 48KB exactly.
// ---------------------------------------------------------------------------
__global__ void __launch_bounds__(256)
attn_kernel(const float* __restrict__ Q, const float* __restrict__ K,
            const float* __restrict__ V, float* __restrict__ O)
{
    __shared__ float Qt[HD][64];
    __shared__ float KP[64][64];
    __shared__ float Vs[64][64];

    int tid = threadIdx.x;
    int qt = blockIdx.x;
    int bh = blockIdx.y;
    int b = bh >> 4, h = bh & 15;
    int q0 = qt * 64;

    const float* Qb = Q + (size_t)b * SEQ * HDIM + (size_t)h * HD;
    const float* Kb = K + (size_t)b * SEQ * HDIM + (size_t)h * HD;
    const float* Vb = V + (size_t)b * SEQ * HDIM + (size_t)h * HD;

    // load Q tile transposed: Qt[d][qrow]
    #pragma unroll
    for (int rep = 0; rep < 4; rep++) {
        int lin = rep * 256 + tid;
        int row = lin >> 4;
        int c4  = (lin & 15) << 2;
        float4 v = *(const float4*)(Qb + (size_t)(q0 + row) * HDIM + c4);
        Qt[c4+0][row] = v.x; Qt[c4+1][row] = v.y; Qt[c4+2][row] = v.z; Qt[c4+3][row] = v.w;
    }

    int ty = tid >> 4, tx = tid & 15;
    float acc[4][4];
    float m[4], lsum[4];
    #pragma unroll
    for (int i = 0; i < 4; i++) {
        m[i] = -1e30f; lsum[i] = 0.f;
        #pragma unroll
        for (int j = 0; j < 4; j++) acc[i][j] = 0.f;
    }
    const float scale = 0.125f;   // 1/sqrt(64)

    for (int t = 0; t < SEQ / 64; t++) {
        __syncthreads();  // prior iter done reading KP/Vs (and Qt store done, iter 0)
        // load K transposed -> KP, V natural -> Vs
        #pragma unroll
        for (int rep = 0; rep < 4; rep++) {
            int lin = rep * 256 + tid;
            int row = lin >> 4;
            int c4  = (lin & 15) << 2;
            float4 kv = *(const float4*)(Kb + (size_t)(t*64 + row) * HDIM + c4);
            KP[c4+0][row] = kv.x; KP[c4+1][row] = kv.y; KP[c4+2][row] = kv.z; KP[c4+3][row] = kv.w;
            float4 vv = *(const float4*)(Vb + (size_t)(t*64 + row) * HDIM + c4);
            *(float4*)&Vs[row][c4] = vv;
        }
        __syncthreads();

        // scores: s[i][j] = sum_d Qt[d][ty*4+i] * KP[d][tx*4+j]
        float s[4][4];
        #pragma unroll
        for (int i = 0; i < 4; i++)
            #pragma unroll
            for (int j = 0; j < 4; j++) s[i][j] = 0.f;
        #pragma unroll 8
        for (int d = 0; d < HD; d++) {
            float4 qv = *(const float4*)&Qt[d][ty*4];
            float4 kv = *(const float4*)&KP[d][tx*4];
            float qa[4] = {qv.x, qv.y, qv.z, qv.w};
            float ka[4] = {kv.x, kv.y, kv.z, kv.w};
            #pragma unroll
            for (int i = 0; i < 4; i++)
                #pragma unroll
                for (int j = 0; j < 4; j++)
                    s[i][j] = fmaf(qa[i], ka[j], s[i][j]);
        }

        // online softmax (row groups of 16 lanes; xor shuffles stay in-group)
        #pragma unroll
        for (int i = 0; i < 4; i++) {
            #pragma unroll
            for (int j = 0; j < 4; j++) s[i][j] *= scale;
            float rm = fmaxf(fmaxf(s[i][0], s[i][1]), fmaxf(s[i][2], s[i][3]));
            #pragma unroll
            for (int o = 8; o; o >>= 1) rm = fmaxf(rm, __shfl_xor_sync(0xffffffffu, rm, o));
            float mn = fmaxf(m[i], rm);
            float al = __expf(m[i] - mn);
            m[i] = mn;
            float rs = 0.f;
            #pragma unroll
            for (int j = 0; j < 4; j++) { s[i][j] = __expf(s[i][j] - mn); rs += s[i][j]; }
            #pragma unroll
            for (int o = 8; o; o >>= 1) rs += __shfl_xor_sync(0xffffffffu, rs, o);
            lsum[i] = lsum[i] * al + rs;
            #pragma unroll
            for (int j = 0; j < 4; j++) acc[i][j] *= al;
        }

        __syncthreads();  // all warps done reading KP (K phase)
        // store P transposed: Pt[k][qrow]
        #pragma unroll
        for (int i = 0; i < 4; i++)
            #pragma unroll
            for (int j = 0; j < 4; j++)
                KP[tx*4+j][ty*4+i] = s[i][j];
        __syncthreads();

        // acc += P @ V : acc[i][j] += sum_k Pt[k][ty*4+i] * Vs[k][tx*4+j]
        #pragma unroll 8
        for (int k = 0; k < 64; k++) {
            float4 pv = *(const float4*)&KP[k][ty*4];
            float4 vv = *(const float4*)&Vs[k][tx*4];
            float pa[4] = {pv.x, pv.y, pv.z, pv.w};
            float va[4] = {vv.x, vv.y, vv.z, vv.w};
            #pragma unroll
            for (int i = 0; i < 4; i++)
                #pragma unroll
                for (int j = 0; j < 4; j++)
                    acc[i][j] = fmaf(pa[i], va[j], acc[i][j]);
        }
    }

    float* Ob = O + (size_t)(b * SEQ + q0) * HDIM + (size_t)h * HD;
    #pragma unroll
    for (int i = 0; i < 4; i++) {
        float inv = 1.0f / lsum[i];
        float4 o = make_float4(acc[i][0]*inv, acc[i][1]*inv, acc[i][2]*inv, acc[i][3]*inv);
        *(float4*)(Ob + (size_t)(ty*4 + i) * HDIM + tx*4) = o;
    }
}

// ---------------------------------------------------------------------------
extern "C" void kernel_launch(void* const* d_in, const int* in_sizes, int n_in,
                              void* d_out, int out_size)
{
    const float* x     = (const float*)d_in[0];
    const float* Wq    = (const float*)d_in[1];
    const float* Wk    = (const float*)d_in[2];
    const float* Wv    = (const float*)d_in[3];
    const float* Wo    = (const float*)d_in[4];
    const float* bo    = (const float*)d_in[5];
    const float* gamma = (const float*)d_in[6];
    const float* beta  = (const float*)d_in[7];
    float* out = (float*)d_out;

    float *xn, *q, *k, *v, *ao;
    cudaGetSymbolAddress((void**)&xn, g_xn);
    cudaGetSymbolAddress((void**)&q,  g_q);
    cudaGetSymbolAddress((void**)&k,  g_k);
    cudaGetSymbolAddress((void**)&v,  g_v);
    cudaGetSymbolAddress((void**)&ao, g_ao);

    // 1. LayerNorm
    ln_kernel<<<MROWS, 256>>>(x, gamma, beta, xn);

    // 2. Fused QKV projections (gridDim.z = 3)
    dim3 ggrid(HDIM / 128, MROWS / 128, 3);
    gemm_nt<0><<<ggrid, 256>>>(xn, Wq, Wk, Wv, q, k, v, nullptr, nullptr);

    // 3. Flash attention
    dim3 agrid(SEQ / 64, BATCH * NH);
    attn_kernel<<<agrid, 256>>>(q, k, v, ao);

    // 4. Output projection + bias + residual
    dim3 ogrid(HDIM / 128, MROWS / 128, 1);
    gemm_nt<1><<<ogrid, 256>>>(ao, Wo, Wo, Wo, out, out, out, bo, x);
}

// round 6
// speedup vs baseline: 1.7349x; 1.7349x over previous
#include <cuda_runtime.h>
#include <math.h>
#include <stdint.h>

#define HDIM 1024
#define NH 16
#define HD 64
#define BATCH 2
#define SEQ 2048
#define MROWS (BATCH*SEQ)   // 4096
#define LN_EPS 1e-5f

// Scratch (allocation-free rule: __device__ globals)
__device__ float g_xn[MROWS*HDIM];
__device__ float g_q [MROWS*HDIM];
__device__ float g_k [MROWS*HDIM];
__device__ float g_v [MROWS*HDIM];
__device__ float g_ao[MROWS*HDIM];

// ---------------------------------------------------------------------------
// helpers
// ---------------------------------------------------------------------------
__device__ __forceinline__ uint32_t f2tf(float x) {
    uint32_t r;
    asm("cvt.rna.tf32.f32 %0, %1;" : "=r"(r) : "f"(x));
    return r;
}

__device__ __forceinline__ void mma8(float* d, const uint32_t* a, const uint32_t* b) {
    asm volatile(
        "mma.sync.aligned.m16n8k8.row.col.f32.tf32.tf32.f32 "
        "{%0,%1,%2,%3},{%4,%5,%6,%7},{%8,%9},{%0,%1,%2,%3};"
        : "+f"(d[0]), "+f"(d[1]), "+f"(d[2]), "+f"(d[3])
        : "r"(a[0]), "r"(a[1]), "r"(a[2]), "r"(a[3]), "r"(b[0]), "r"(b[1]));
}

__device__ __forceinline__ uint32_t smem_u32(const void* p) {
    return (uint32_t)__cvta_generic_to_shared(p);
}
__device__ __forceinline__ void cpa16(uint32_t s, const void* g) {
    asm volatile("cp.async.cg.shared.global [%0], [%1], 16;" :: "r"(s), "l"(g));
}
#define CP_COMMIT asm volatile("cp.async.commit_group;")
#define CP_WAIT0  asm volatile("cp.async.wait_group 0;")
#define CP_WAIT1  asm volatile("cp.async.wait_group 1;")

// ---------------------------------------------------------------------------
// LayerNorm: one block per row (1024 cols), 256 threads, float4 per thread.
// ---------------------------------------------------------------------------
__global__ void ln_kernel(const float* __restrict__ x,
                          const float* __restrict__ gamma,
                          const float* __restrict__ beta,
                          float* __restrict__ xn)
{
    int row = blockIdx.x;
    int tid = threadIdx.x;
    const float4* xr = (const float4*)(x + (size_t)row * HDIM);
    float4 v = xr[tid];
    float s  = v.x + v.y + v.z + v.w;
    float ss = v.x*v.x + v.y*v.y + v.z*v.z + v.w*v.w;
    #pragma unroll
    for (int o = 16; o; o >>= 1) {
        s  += __shfl_xor_sync(0xffffffffu, s,  o);
        ss += __shfl_xor_sync(0xffffffffu, ss, o);
    }
    __shared__ float red0[8], red1[8];
    int w = tid >> 5, l = tid & 31;
    if (l == 0) { red0[w] = s; red1[w] = ss; }
    __syncthreads();
    float ts = 0.f, tss = 0.f;
    #pragma unroll
    for (int i = 0; i < 8; i++) { ts += red0[i]; tss += red1[i]; }
    float mu  = ts * (1.0f / HDIM);
    float var = tss * (1.0f / HDIM) - mu * mu;
    float inv = rsqrtf(var + LN_EPS);

    float4 g = ((const float4*)gamma)[tid];
    float4 b = ((const float4*)beta)[tid];
    float4 o;
    o.x = (v.x - mu) * inv * g.x + b.x;
    o.y = (v.y - mu) * inv * g.y + b.y;
    o.z = (v.z - mu) * inv * g.z + b.z;
    o.w = (v.w - mu) * inv * g.w + b.w;
    ((float4*)(xn + (size_t)row * HDIM))[tid] = o;
}

// ---------------------------------------------------------------------------
// Tensor-core NT GEMM via mma.sync tf32 with 3xTF32 (fp32-class accuracy).
// C[M,N] = A[M,K] * W[N,K]^T.  BM=BN=128, BK=16, 256 threads (8 warps, 2x4),
// warp tile 64x32 (m-frags 4, n-frags 4).  cp.async double-buffered smem.
// EPI=1: C += bias + resid.  gridDim.z selects (W,C) for fused QKV.
// ---------------------------------------------------------------------------
template <int EPI>
__global__ void __launch_bounds__(256)
gemm_tc(const float* __restrict__ A,
        const float* __restrict__ W0, const float* __restrict__ W1, const float* __restrict__ W2,
        float* __restrict__ C0, float* __restrict__ C1, float* __restrict__ C2,
        const float* __restrict__ bias, const float* __restrict__ resid)
{
    const int SA = 20;                       // padded row stride (floats)
    __shared__ float As[2][128 * SA];
    __shared__ float Bs[2][128 * SA];

    int z = blockIdx.z;
    const float* W = (z == 0) ? W0 : (z == 1 ? W1 : W2);
    float*       C = (z == 0) ? C0 : (z == 1 ? C1 : C2);

    int tid  = threadIdx.x;
    int m0   = blockIdx.y * 128;
    int n0   = blockIdx.x * 128;
    int w    = tid >> 5, lane = tid & 31;
    int gid  = lane >> 2, tig = lane & 3;
    int wr   = w >> 2, wc = w & 3;           // warp grid 2 (M) x 4 (N)

    float acc[4][4][4];
    #pragma unroll
    for (int i = 0; i < 4; i++)
        #pragma unroll
        for (int j = 0; j < 4; j++)
            #pragma unroll
            for (int e = 0; e < 4; e++) acc[i][j][e] = 0.f;

    auto issue = [&](int stage, int k0) {
        #pragma unroll
        for (int i = 0; i < 2; i++) {
            int ch  = tid * 2 + i;           // 0..511
            int row = ch >> 2, off = (ch & 3) << 2;
            cpa16(smem_u32(&As[stage][row * SA + off]),
                  A + (size_t)(m0 + row) * HDIM + k0 + off);
            cpa16(smem_u32(&Bs[stage][row * SA + off]),
                  W + (size_t)(n0 + row) * HDIM + k0 + off);
        }
        CP_COMMIT;
    };

    issue(0, 0);
    const int NC = HDIM / 16;                // 64 chunks
    for (int c = 0; c < NC; c++) {
        int buf = c & 1;
        if (c + 1 < NC) { issue(buf ^ 1, (c + 1) * 16); CP_WAIT1; }
        else            { CP_WAIT0; }
        __syncthreads();

        #pragma unroll
        for (int ks = 0; ks < 2; ks++) {
            uint32_t bh[4][2], bl[4][2];
            #pragma unroll
            for (int nf = 0; nf < 4; nf++) {
                const float* bp = &Bs[buf][(wc * 32 + nf * 8 + gid) * SA + ks * 8 + tig];
                float b0 = bp[0], b1 = bp[4];
                bh[nf][0] = f2tf(b0);
                bl[nf][0] = f2tf(b0 - __uint_as_float(bh[nf][0]));
                bh[nf][1] = f2tf(b1);
                bl[nf][1] = f2tf(b1 - __uint_as_float(bh[nf][1]));
            }
            #pragma unroll
            for (int mf = 0; mf < 4; mf++) {
                const float* ap = &As[buf][(wr * 64 + mf * 16 + gid) * SA + ks * 8 + tig];
                float a0 = ap[0], a1 = ap[8 * SA], a2 = ap[4], a3 = ap[8 * SA + 4];
                uint32_t ah[4] = { f2tf(a0), f2tf(a1), f2tf(a2), f2tf(a3) };
                uint32_t al[4] = { f2tf(a0 - __uint_as_float(ah[0])),
                                   f2tf(a1 - __uint_as_float(ah[1])),
                                   f2tf(a2 - __uint_as_float(ah[2])),
                                   f2tf(a3 - __uint_as_float(ah[3])) };
                #pragma unroll
                for (int nf = 0; nf < 4; nf++) {
                    mma8(acc[mf][nf], ah, bh[nf]);
                    mma8(acc[mf][nf], ah, bl[nf]);
                    mma8(acc[mf][nf], al, bh[nf]);
                }
            }
        }
        __syncthreads();
    }

    #pragma unroll
    for (int mf = 0; mf < 4; mf++) {
        int r0 = m0 + wr * 64 + mf * 16 + gid;
        #pragma unroll
        for (int nf = 0; nf < 4; nf++) {
            int col = n0 + wc * 32 + nf * 8 + 2 * tig;
            float2 v0 = make_float2(acc[mf][nf][0], acc[mf][nf][1]);
            float2 v1 = make_float2(acc[mf][nf][2], acc[mf][nf][3]);
            if (EPI) {
                float2 bi  = *(const float2*)(bias + col);
                float2 rA  = *(const float2*)(resid + (size_t)r0 * HDIM + col);
                float2 rB  = *(const float2*)(resid + (size_t)(r0 + 8) * HDIM + col);
                v0.x += bi.x + rA.x; v0.y += bi.y + rA.y;
                v1.x += bi.x + rB.x; v1.y += bi.y + rB.y;
            }
            *(float2*)(C + (size_t)r0 * HDIM + col)       = v0;
            *(float2*)(C + (size_t)(r0 + 8) * HDIM + col) = v1;
        }
    }
}

// ---------------------------------------------------------------------------
// Flash attention on tensor cores.  Block = 128 q-rows x one (b,h);
// 8 warps, warp tile m16 x n64 (full key tile).  QK^T 3xTF32, PV 1xTF32.
// K/V tiles (64 keys) via cp.async; P stays in registers (C-frag -> A-frag
// transpose via quad shuffles).
// ---------------------------------------------------------------------------
__global__ void __launch_bounds__(256)
attn_tc(const float* __restrict__ Q, const float* __restrict__ K,
        const float* __restrict__ V, float* __restrict__ O)
{
    const int SK = 68, SV = 72;
    __shared__ float Ks[64 * SK];            // K tile [key][d]
    __shared__ float Vsm[64 * SV];           // V tile [key][d]

    int tid = threadIdx.x, w = tid >> 5, lane = tid & 31;
    int gid = lane >> 2, tig = lane & 3;
    int bh = blockIdx.y, b = bh >> 4, h = bh & 15;
    int q0 = blockIdx.x * 128;

    const float* Qb = Q + (size_t)b * SEQ * HDIM + h * 64;
    const float* Kb = K + (size_t)b * SEQ * HDIM + h * 64;
    const float* Vb = V + (size_t)b * SEQ * HDIM + h * 64;

    // Q fragments (scaled by 1/sqrt(HD)=0.125, exact power of 2)
    int r0 = q0 + w * 16 + gid;
    float qf[8][4];
    #pragma unroll
    for (int ks = 0; ks < 8; ks++) {
        int c = ks * 8 + tig;
        qf[ks][0] = Qb[(size_t)r0 * HDIM + c] * 0.125f;
        qf[ks][1] = Qb[(size_t)(r0 + 8) * HDIM + c] * 0.125f;
        qf[ks][2] = Qb[(size_t)r0 * HDIM + c + 4] * 0.125f;
        qf[ks][3] = Qb[(size_t)(r0 + 8) * HDIM + c + 4] * 0.125f;
    }

    float o[8][4];
    #pragma unroll
    for (int nf = 0; nf < 8; nf++)
        #pragma unroll
        for (int e = 0; e < 4; e++) o[nf][e] = 0.f;
    float mA = -1e30f, mB = -1e30f, lA = 0.f, lB = 0.f;

    auto load_tile = [&](int t) {
        #pragma unroll
        for (int i = 0; i < 4; i++) {
            int ch  = i * 256 + tid;         // 0..1023
            int row = ch >> 4, off = (ch & 15) << 2;
            cpa16(smem_u32(&Ks[row * SK + off]),  Kb + (size_t)(t * 64 + row) * HDIM + off);
            cpa16(smem_u32(&Vsm[row * SV + off]), Vb + (size_t)(t * 64 + row) * HDIM + off);
        }
        CP_COMMIT;
    };

    load_tile(0);
    const int NT = SEQ / 64;                 // 32 key tiles
    for (int t = 0; t < NT; t++) {
        CP_WAIT0;
        __syncthreads();

        // ---- scores S = (Q/8) K^T  (3xTF32) ----
        float s[8][4];
        #pragma unroll
        for (int nf = 0; nf < 8; nf++)
            #pragma unroll
            for (int e = 0; e < 4; e++) s[nf][e] = 0.f;

        #pragma unroll
        for (int ks = 0; ks < 8; ks++) {
            uint32_t ah[4], al[4];
            #pragma unroll
            for (int e = 0; e < 4; e++) {
                ah[e] = f2tf(qf[ks][e]);
                al[e] = f2tf(qf[ks][e] - __uint_as_float(ah[e]));
            }
            #pragma unroll
            for (int nf = 0; nf < 8; nf++) {
                const float* bp = &Ks[(nf * 8 + gid) * SK + ks * 8 + tig];
                float b0 = bp[0], b1 = bp[4];
                uint32_t bhv[2] = { f2tf(b0), f2tf(b1) };
                uint32_t blv[2] = { f2tf(b0 - __uint_as_float(bhv[0])),
                                    f2tf(b1 - __uint_as_float(bhv[1])) };
                mma8(s[nf], ah, bhv);
                mma8(s[nf], ah, blv);
                mma8(s[nf], al, bhv);
            }
        }

        // ---- online softmax (row A = gid, row B = gid+8 within warp m16) ----
        float mxA = -1e30f, mxB = -1e30f;
        #pragma unroll
        for (int nf = 0; nf < 8; nf++) {
            mxA = fmaxf(mxA, fmaxf(s[nf][0], s[nf][1]));
            mxB = fmaxf(mxB, fmaxf(s[nf][2], s[nf][3]));
        }
        #pragma unroll
        for (int ofs = 1; ofs <= 2; ofs <<= 1) {
            mxA = fmaxf(mxA, __shfl_xor_sync(0xffffffffu, mxA, ofs));
            mxB = fmaxf(mxB, __shfl_xor_sync(0xffffffffu, mxB, ofs));
        }
        float mnA = fmaxf(mA, mxA), mnB = fmaxf(mB, mxB);
        float alpA = __expf(mA - mnA), alpB = __expf(mB - mnB);
        mA = mnA; mB = mnB;

        float rsA = 0.f, rsB = 0.f;
        #pragma unroll
        for (int nf = 0; nf < 8; nf++) {
            s[nf][0] = __expf(s[nf][0] - mnA);
            s[nf][1] = __expf(s[nf][1] - mnA);
            s[nf][2] = __expf(s[nf][2] - mnB);
            s[nf][3] = __expf(s[nf][3] - mnB);
            rsA += s[nf][0] + s[nf][1];
            rsB += s[nf][2] + s[nf][3];
        }
        #pragma unroll
        for (int ofs = 1; ofs <= 2; ofs <<= 1) {
            rsA += __shfl_xor_sync(0xffffffffu, rsA, ofs);
            rsB += __shfl_xor_sync(0xffffffffu, rsB, ofs);
        }
        lA = lA * alpA + rsA;
        lB = lB * alpB + rsB;
        #pragma unroll
        for (int nf = 0; nf < 8; nf++) {
            o[nf][0] *= alpA; o[nf][1] *= alpA;
            o[nf][2] *= alpB; o[nf][3] *= alpB;
        }

        // ---- O += P V  (P: C-frag -> A-frag via quad shuffles; 1xTF32) ----
        #pragma unroll
        for (int kg = 0; kg < 8; kg++) {
            int s0l = (lane & ~3) | (tig >> 1);
            int s2l = s0l + 2;
            float v00 = __shfl_sync(0xffffffffu, s[kg][0], s0l);
            float v01 = __shfl_sync(0xffffffffu, s[kg][1], s0l);
            float v10 = __shfl_sync(0xffffffffu, s[kg][2], s0l);
            float v11 = __shfl_sync(0xffffffffu, s[kg][3], s0l);
            float v20 = __shfl_sync(0xffffffffu, s[kg][0], s2l);
            float v21 = __shfl_sync(0xffffffffu, s[kg][1], s2l);
            float v30 = __shfl_sync(0xffffffffu, s[kg][2], s2l);
            float v31 = __shfl_sync(0xffffffffu, s[kg][3], s2l);
            bool odd = (tig & 1);
            uint32_t aP[4] = { f2tf(odd ? v01 : v00),
                               f2tf(odd ? v11 : v10),
                               f2tf(odd ? v21 : v20),
                               f2tf(odd ? v31 : v30) };
            #pragma unroll
            for (int nf = 0; nf < 8; nf++) {
                const float* vp = &Vsm[(kg * 8 + tig) * SV + nf * 8 + gid];
                uint32_t bv[2] = { f2tf(vp[0]), f2tf(vp[4 * SV]) };
                mma8(o[nf], aP, bv);
            }
        }

        __syncthreads();
        if (t + 1 < NT) load_tile(t + 1);
    }

    float iA = 1.0f / lA, iB = 1.0f / lB;
    float* Ob = O + (size_t)(b * SEQ) * HDIM + h * 64;
    #pragma unroll
    for (int nf = 0; nf < 8; nf++) {
        int col = nf * 8 + 2 * tig;
        *(float2*)(Ob + (size_t)r0 * HDIM + col)       = make_float2(o[nf][0] * iA, o[nf][1] * iA);
        *(float2*)(Ob + (size_t)(r0 + 8) * HDIM + col) = make_float2(o[nf][2] * iB, o[nf][3] * iB);
    }
}

// ---------------------------------------------------------------------------
extern "C" void kernel_launch(void* const* d_in, const int* in_sizes, int n_in,
                              void* d_out, int out_size)
{
    const float* x     = (const float*)d_in[0];
    const float* Wq    = (const float*)d_in[1];
    const float* Wk    = (const float*)d_in[2];
    const float* Wv    = (const float*)d_in[3];
    const float* Wo    = (const float*)d_in[4];
    const float* bo    = (const float*)d_in[5];
    const float* gamma = (const float*)d_in[6];
    const float* beta  = (const float*)d_in[7];
    float* out = (float*)d_out;

    float *xn, *q, *k, *v, *ao;
    cudaGetSymbolAddress((void**)&xn, g_xn);
    cudaGetSymbolAddress((void**)&q,  g_q);
    cudaGetSymbolAddress((void**)&k,  g_k);
    cudaGetSymbolAddress((void**)&v,  g_v);
    cudaGetSymbolAddress((void**)&ao, g_ao);

    // 1. LayerNorm
    ln_kernel<<<MROWS, 256>>>(x, gamma, beta, xn);

    // 2. Fused QKV projections (tensor cores, gridDim.z = 3)
    dim3 ggrid(HDIM / 128, MROWS / 128, 3);
    gemm_tc<0><<<ggrid, 256>>>(xn, Wq, Wk, Wv, q, k, v, nullptr, nullptr);

    // 3. Flash attention (tensor cores)
    dim3 agrid(SEQ / 128, BATCH * NH);
    attn_tc<<<agrid, 256>>>(q, k, v, ao);

    // 4. Output projection + bias + residual (tensor cores)
    dim3 ogrid(HDIM / 128, MROWS / 128, 1);
    gemm_tc<1><<<ogrid, 256>>>(ao, Wo, Wo, Wo, out, out, out, bo, x);
}

// round 8
// speedup vs baseline: 2.5569x; 1.4738x over previous
#include <cuda_runtime.h>
#include <cuda_bf16.h>
#include <math.h>
#include <stdint.h>

#define HDIM 1024
#define NH 16
#define HD 64
#define BATCH 2
#define SEQ 2048
#define MROWS (BATCH*SEQ)   // 4096
#define LN_EPS 1e-5f
#define WSZ (HDIM*HDIM)

typedef __nv_bfloat16 bf16;

// ---------------- scratch (allocation-free rule: __device__ globals) --------
__device__ bf16 g_xnh[MROWS*HDIM], g_xnl[MROWS*HDIM];
__device__ bf16 g_qh [MROWS*HDIM], g_ql [MROWS*HDIM];
__device__ bf16 g_kh [MROWS*HDIM], g_kl [MROWS*HDIM];
__device__ bf16 g_vh [MROWS*HDIM], g_vl [MROWS*HDIM];
__device__ bf16 g_aoh[MROWS*HDIM], g_aol[MROWS*HDIM];
__device__ bf16 g_wh[4*WSZ], g_wl[4*WSZ];

// ---------------- helpers ---------------------------------------------------
__device__ __forceinline__ uint32_t packbf(float a, float b) {
    __nv_bfloat162 t = __floats2bfloat162_rn(a, b);
    return *reinterpret_cast<uint32_t*>(&t);
}
__device__ __forceinline__ void split2(float a, float b, uint32_t& hi, uint32_t& lo) {
    float ha = __bfloat162float(__float2bfloat16_rn(a));
    float hb = __bfloat162float(__float2bfloat16_rn(b));
    hi = packbf(ha, hb);
    lo = packbf(a - ha, b - hb);
}
__device__ __forceinline__ void mma16(float* d, const uint32_t* a, uint32_t b0, uint32_t b1) {
    asm volatile(
        "mma.sync.aligned.m16n8k16.row.col.f32.bf16.bf16.f32 "
        "{%0,%1,%2,%3},{%4,%5,%6,%7},{%8,%9},{%0,%1,%2,%3};"
        : "+f"(d[0]), "+f"(d[1]), "+f"(d[2]), "+f"(d[3])
        : "r"(a[0]), "r"(a[1]), "r"(a[2]), "r"(a[3]), "r"(b0), "r"(b1));
}
__device__ __forceinline__ uint32_t smem_u32(const void* p) {
    return (uint32_t)__cvta_generic_to_shared(p);
}
__device__ __forceinline__ void cpa16(uint32_t s, const void* g) {
    asm volatile("cp.async.cg.shared.global [%0], [%1], 16;" :: "r"(s), "l"(g));
}
__device__ __forceinline__ void ldsm_x2_t(uint32_t& r0, uint32_t& r1, uint32_t addr) {
    asm volatile("ldmatrix.sync.aligned.m8n8.x2.trans.shared.b16 {%0,%1},[%2];"
                 : "=r"(r0), "=r"(r1) : "r"(addr));
}
#define CP_COMMIT asm volatile("cp.async.commit_group;")
#define CP_WAIT0  asm volatile("cp.async.wait_group 0;")
#define CP_WAIT1  asm volatile("cp.async.wait_group 1;")

// ---------------- weight split: fp32 -> bf16 hi/lo --------------------------
__global__ void split_arr(const float* __restrict__ src, bf16* __restrict__ h,
                          bf16* __restrict__ l)
{
    int i = blockIdx.x * 256 + threadIdx.x;
    float4 v = ((const float4*)src)[i];
    uint32_t h0, l0, h1, l1;
    split2(v.x, v.y, h0, l0);
    split2(v.z, v.w, h1, l1);
    ((uint32_t*)h)[2*i]   = h0; ((uint32_t*)h)[2*i+1] = h1;
    ((uint32_t*)l)[2*i]   = l0; ((uint32_t*)l)[2*i+1] = l1;
}

// ---------------- LayerNorm -> bf16 hi/lo -----------------------------------
__global__ void ln_kernel(const float* __restrict__ x,
                          const float* __restrict__ gamma,
                          const float* __restrict__ beta,
                          bf16* __restrict__ xnh, bf16* __restrict__ xnl)
{
    int row = blockIdx.x;
    int tid = threadIdx.x;
    const float4* xr = (const float4*)(x + (size_t)row * HDIM);
    float4 v = xr[tid];
    float s  = v.x + v.y + v.z + v.w;
    float ss = v.x*v.x + v.y*v.y + v.z*v.z + v.w*v.w;
    #pragma unroll
    for (int o = 16; o; o >>= 1) {
        s  += __shfl_xor_sync(0xffffffffu, s,  o);
        ss += __shfl_xor_sync(0xffffffffu, ss, o);
    }
    __shared__ float red0[8], red1[8];
    int w = tid >> 5, l = tid & 31;
    if (l == 0) { red0[w] = s; red1[w] = ss; }
    __syncthreads();
    float ts = 0.f, tss = 0.f;
    #pragma unroll
    for (int i = 0; i < 8; i++) { ts += red0[i]; tss += red1[i]; }
    float mu  = ts * (1.0f / HDIM);
    float var = tss * (1.0f / HDIM) - mu * mu;
    float inv = rsqrtf(var + LN_EPS);

    float4 g = ((const float4*)gamma)[tid];
    float4 b = ((const float4*)beta)[tid];
    float o0 = (v.x - mu) * inv * g.x + b.x;
    float o1 = (v.y - mu) * inv * g.y + b.y;
    float o2 = (v.z - mu) * inv * g.z + b.z;
    float o3 = (v.w - mu) * inv * g.w + b.w;
    uint32_t h0, l0, h1, l1;
    split2(o0, o1, h0, l0);
    split2(o2, o3, h1, l1);
    uint32_t base = row * (HDIM/2) + tid * 2;
    ((uint32_t*)xnh)[base]   = h0; ((uint32_t*)xnh)[base+1] = h1;
    ((uint32_t*)xnl)[base]   = l0; ((uint32_t*)xnl)[base+1] = l1;
}

// ---------------- 3-term bf16 NT GEMM ---------------------------------------
// C[M,N] = A * W^T with A=Ah+Al, W=Wh+Wl (bf16 splits), fp32 accum.
// BM=BN=128, BK=16, 256 thr (8 warps 2x4), warp tile 64x32 (mf4 x nf4).
// FINAL=0: epilogue splits C into (Ch,Cl) bf16 pairs (per-z outputs).
// FINAL=1: fp32 C = acc + bias + resid.
template <int FINAL>
__global__ void __launch_bounds__(256, 2)
gemm_bf3(const bf16* __restrict__ Ah, const bf16* __restrict__ Al,
         const bf16* __restrict__ Wh0, const bf16* __restrict__ Wl0,
         bf16* C0h, bf16* C0l, bf16* C1h, bf16* C1l, bf16* C2h, bf16* C2l,
         float* __restrict__ Cf, const float* __restrict__ bias,
         const float* __restrict__ resid)
{
    const int SA = 24;   // padded row stride (bf16)
    __shared__ bf16 sAh[2][128*SA], sAl[2][128*SA];
    __shared__ bf16 sBh[2][128*SA], sBl[2][128*SA];

    int z = blockIdx.z;
    const bf16* Wh = Wh0 + (size_t)z * WSZ;
    const bf16* Wl = Wl0 + (size_t)z * WSZ;
    bf16* Ch = (z == 0) ? C0h : (z == 1 ? C1h : C2h);
    bf16* Cl = (z == 0) ? C0l : (z == 1 ? C1l : C2l);

    int tid  = threadIdx.x;
    int m0   = blockIdx.y * 128;
    int n0   = blockIdx.x * 128;
    int w    = tid >> 5, lane = tid & 31;
    int gid  = lane >> 2, tig = lane & 3;
    int wr   = w >> 2, wc = w & 3;

    float acc[4][4][4];
    #pragma unroll
    for (int i = 0; i < 4; i++)
        #pragma unroll
        for (int j = 0; j < 4; j++)
            #pragma unroll
            for (int e = 0; e < 4; e++) acc[i][j][e] = 0.f;

    int lrow = tid >> 1;              // 0..127
    int lofs = (tid & 1) * 8;         // 0 or 8
    auto issue = [&](int stage, int k0) {
        uint32_t d0 = smem_u32(&sAh[stage][lrow*SA + lofs]);
        uint32_t d1 = smem_u32(&sAl[stage][lrow*SA + lofs]);
        uint32_t d2 = smem_u32(&sBh[stage][lrow*SA + lofs]);
        uint32_t d3 = smem_u32(&sBl[stage][lrow*SA + lofs]);
        size_t ma = (size_t)(m0 + lrow) * HDIM + k0 + lofs;
        size_t nb = (size_t)(n0 + lrow) * HDIM + k0 + lofs;
        cpa16(d0, Ah + ma);
        cpa16(d1, Al + ma);
        cpa16(d2, Wh + nb);
        cpa16(d3, Wl + nb);
        CP_COMMIT;
    };

    issue(0, 0);
    const int NC = HDIM / 16;
    for (int c = 0; c < NC; c++) {
        int buf = c & 1;
        if (c + 1 < NC) { issue(buf ^ 1, (c + 1) * 16); CP_WAIT1; }
        else            { CP_WAIT0; }
        __syncthreads();

        uint32_t bh[4][2], bl[4][2];
        #pragma unroll
        for (int nf = 0; nf < 4; nf++) {
            int base = (wc*32 + nf*8 + gid) * SA + 2*tig;
            bh[nf][0] = *(const uint32_t*)&sBh[buf][base];
            bh[nf][1] = *(const uint32_t*)&sBh[buf][base + 8];
            bl[nf][0] = *(const uint32_t*)&sBl[buf][base];
            bl[nf][1] = *(const uint32_t*)&sBl[buf][base + 8];
        }
        #pragma unroll
        for (int mf = 0; mf < 4; mf++) {
            int ab = (wr*64 + mf*16 + gid) * SA + 2*tig;
            uint32_t ah[4], al[4];
            ah[0] = *(const uint32_t*)&sAh[buf][ab];
            ah[1] = *(const uint32_t*)&sAh[buf][ab + 8*SA];
            ah[2] = *(const uint32_t*)&sAh[buf][ab + 8];
            ah[3] = *(const uint32_t*)&sAh[buf][ab + 8*SA + 8];
            al[0] = *(const uint32_t*)&sAl[buf][ab];
            al[1] = *(const uint32_t*)&sAl[buf][ab + 8*SA];
            al[2] = *(const uint32_t*)&sAl[buf][ab + 8];
            al[3] = *(const uint32_t*)&sAl[buf][ab + 8*SA + 8];
            #pragma unroll
            for (int nf = 0; nf < 4; nf++) {
                mma16(acc[mf][nf], ah, bh[nf][0], bh[nf][1]);
                mma16(acc[mf][nf], ah, bl[nf][0], bl[nf][1]);
                mma16(acc[mf][nf], al, bh[nf][0], bh[nf][1]);
            }
        }
        __syncthreads();
    }

    #pragma unroll
    for (int mf = 0; mf < 4; mf++) {
        int r0 = m0 + wr*64 + mf*16 + gid;
        #pragma unroll
        for (int nf = 0; nf < 4; nf++) {
            int col = n0 + wc*32 + nf*8 + 2*tig;
            if (FINAL) {
                float2 bi = *(const float2*)(bias + col);
                float2 rA = *(const float2*)(resid + (size_t)r0 * HDIM + col);
                float2 rB = *(const float2*)(resid + (size_t)(r0+8) * HDIM + col);
                *(float2*)(Cf + (size_t)r0 * HDIM + col) =
                    make_float2(acc[mf][nf][0] + bi.x + rA.x, acc[mf][nf][1] + bi.y + rA.y);
                *(float2*)(Cf + (size_t)(r0+8) * HDIM + col) =
                    make_float2(acc[mf][nf][2] + bi.x + rB.x, acc[mf][nf][3] + bi.y + rB.y);
            } else {
                uint32_t h0, l0, h1, l1;
                split2(acc[mf][nf][0], acc[mf][nf][1], h0, l0);
                split2(acc[mf][nf][2], acc[mf][nf][3], h1, l1);
                size_t iA = ((size_t)r0 * HDIM + col) >> 1;
                size_t iB = ((size_t)(r0+8) * HDIM + col) >> 1;
                ((uint32_t*)Ch)[iA] = h0; ((uint32_t*)Cl)[iA] = l0;
                ((uint32_t*)Ch)[iB] = h1; ((uint32_t*)Cl)[iB] = l1;
            }
        }
    }
}

// ---------------- flash attention, 3-term bf16 ------------------------------
// Block: 128 q-rows x one (b,h); 8 warps, warp tile m16 x 64 keys x 64 d.
// QK: Qh/Ql x Kh/Kl (3 mma).  PV: P split in regs x Vh/Vl (3 mma), V frags
// via ldmatrix.trans.  K/V smem double-buffered via cp.async.
#define ATT_S 72
#define ATT_ARR (64*ATT_S)          // elems per array
#define ATT_STAGE (4*ATT_ARR)       // Kh,Kl,Vh,Vl
#define ATT_SMEM (2*ATT_STAGE*2)    // bytes = 73728

__global__ void __launch_bounds__(256)
attn_bf(const bf16* __restrict__ qh, const bf16* __restrict__ ql,
        const bf16* __restrict__ kh, const bf16* __restrict__ kl,
        const bf16* __restrict__ vh, const bf16* __restrict__ vl,
        bf16* __restrict__ aoh, bf16* __restrict__ aol)
{
    extern __shared__ bf16 sm[];

    int tid = threadIdx.x, w = tid >> 5, lane = tid & 31;
    int gid = lane >> 2, tig = lane & 3;
    int bh = blockIdx.y, b = bh >> 4, h = bh & 15;
    int q0 = blockIdx.x * 128;

    size_t rowg = (size_t)b * SEQ + q0 + w*16 + gid;

    // Q fragments: hi/lo, 4 k-groups of 16
    uint32_t qfh[4][4], qfl[4][4];
    #pragma unroll
    for (int kg = 0; kg < 4; kg++) {
        int cb = h*64 + kg*16 + 2*tig;
        size_t i00 = rowg * HDIM + cb;
        size_t i10 = (rowg + 8) * HDIM + cb;
        qfh[kg][0] = *(const uint32_t*)&qh[i00];
        qfh[kg][1] = *(const uint32_t*)&qh[i10];
        qfh[kg][2] = *(const uint32_t*)&qh[i00 + 8];
        qfh[kg][3] = *(const uint32_t*)&qh[i10 + 8];
        qfl[kg][0] = *(const uint32_t*)&ql[i00];
        qfl[kg][1] = *(const uint32_t*)&ql[i10];
        qfl[kg][2] = *(const uint32_t*)&ql[i00 + 8];
        qfl[kg][3] = *(const uint32_t*)&ql[i10 + 8];
    }

    float o[8][4];
    #pragma unroll
    for (int nf = 0; nf < 8; nf++)
        #pragma unroll
        for (int e = 0; e < 4; e++) o[nf][e] = 0.f;
    float mA = -1e30f, mB = -1e30f, lA = 0.f, lB = 0.f;

    const bf16* srcs[4] = { kh, kl, vh, vl };
    auto load_tile = [&](int stage, int t) {
        #pragma unroll
        for (int i = 0; i < 8; i++) {
            int ch  = i * 256 + tid;          // 0..2047
            int arr = ch >> 9;
            int r   = (ch >> 3) & 63;
            int c8  = (ch & 7) * 8;
            const bf16* src = srcs[arr] +
                ((size_t)b * SEQ + t*64 + r) * HDIM + h*64 + c8;
            cpa16(smem_u32(&sm[stage*ATT_STAGE + arr*ATT_ARR + r*ATT_S + c8]), src);
        }
        CP_COMMIT;
    };

    load_tile(0, 0);
    const int NT = SEQ / 64;
    for (int t = 0; t < NT; t++) {
        int buf = t & 1;
        if (t + 1 < NT) { load_tile(buf ^ 1, t + 1); CP_WAIT1; }
        else            { CP_WAIT0; }
        __syncthreads();

        const bf16* Kh_s = sm + buf*ATT_STAGE;
        const bf16* Kl_s = Kh_s + ATT_ARR;
        const bf16* Vh_s = Kh_s + 2*ATT_ARR;
        const bf16* Vl_s = Kh_s + 3*ATT_ARR;

        // ---- scores ----
        float s[8][4];
        #pragma unroll
        for (int nf = 0; nf < 8; nf++)
            #pragma unroll
            for (int e = 0; e < 4; e++) s[nf][e] = 0.f;

        #pragma unroll
        for (int kg = 0; kg < 4; kg++) {
            #pragma unroll
            for (int nf = 0; nf < 8; nf++) {
                int base = (nf*8 + gid) * ATT_S + kg*16 + 2*tig;
                uint32_t kh0 = *(const uint32_t*)&Kh_s[base];
                uint32_t kh1 = *(const uint32_t*)&Kh_s[base + 8];
                uint32_t kl0 = *(const uint32_t*)&Kl_s[base];
                uint32_t kl1 = *(const uint32_t*)&Kl_s[base + 8];
                mma16(s[nf], qfh[kg], kh0, kh1);
                mma16(s[nf], qfh[kg], kl0, kl1);
                mma16(s[nf], qfl[kg], kh0, kh1);
            }
        }

        // ---- online softmax (scale 1/sqrt(64)=0.125 exact) ----
        #pragma unroll
        for (int nf = 0; nf < 8; nf++)
            #pragma unroll
            for (int e = 0; e < 4; e++) s[nf][e] *= 0.125f;

        float mxA = -1e30f, mxB = -1e30f;
        #pragma unroll
        for (int nf = 0; nf < 8; nf++) {
            mxA = fmaxf(mxA, fmaxf(s[nf][0], s[nf][1]));
            mxB = fmaxf(mxB, fmaxf(s[nf][2], s[nf][3]));
        }
        #pragma unroll
        for (int ofs = 1; ofs <= 2; ofs <<= 1) {
            mxA = fmaxf(mxA, __shfl_xor_sync(0xffffffffu, mxA, ofs));
            mxB = fmaxf(mxB, __shfl_xor_sync(0xffffffffu, mxB, ofs));
        }
        float mnA = fmaxf(mA, mxA), mnB = fmaxf(mB, mxB);
        float alpA = __expf(mA - mnA), alpB = __expf(mB - mnB);
        mA = mnA; mB = mnB;

        float rsA = 0.f, rsB = 0.f;
        #pragma unroll
        for (int nf = 0; nf < 8; nf++) {
            s[nf][0] = __expf(s[nf][0] - mnA);
            s[nf][1] = __expf(s[nf][1] - mnA);
            s[nf][2] = __expf(s[nf][2] - mnB);
            s[nf][3] = __expf(s[nf][3] - mnB);
            rsA += s[nf][0] + s[nf][1];
            rsB += s[nf][2] + s[nf][3];
        }
        #pragma unroll
        for (int ofs = 1; ofs <= 2; ofs <<= 1) {
            rsA += __shfl_xor_sync(0xffffffffu, rsA, ofs);
            rsB += __shfl_xor_sync(0xffffffffu, rsB, ofs);
        }
        lA = lA * alpA + rsA;
        lB = lB * alpB + rsB;
        #pragma unroll
        for (int nf = 0; nf < 8; nf++) {
            o[nf][0] *= alpA; o[nf][1] *= alpA;
            o[nf][2] *= alpB; o[nf][3] *= alpB;
        }

        // ---- O += P V : P C-frag packs directly into bf16 A-frags ----
        #pragma unroll
        for (int kg = 0; kg < 4; kg++) {
            uint32_t aPh[4], aPl[4];
            split2(s[2*kg][0],   s[2*kg][1],   aPh[0], aPl[0]);
            split2(s[2*kg][2],   s[2*kg][3],   aPh[1], aPl[1]);
            split2(s[2*kg+1][0], s[2*kg+1][1], aPh[2], aPl[2]);
            split2(s[2*kg+1][2], s[2*kg+1][3], aPh[3], aPl[3]);
            int vrow = kg*16 + (lane & 15);
            #pragma unroll
            for (int nf = 0; nf < 8; nf++) {
                uint32_t vh0, vh1, vl0, vl1;
                ldsm_x2_t(vh0, vh1, smem_u32(&Vh_s[vrow*ATT_S + nf*8]));
                ldsm_x2_t(vl0, vl1, smem_u32(&Vl_s[vrow*ATT_S + nf*8]));
                mma16(o[nf], aPh, vh0, vh1);
                mma16(o[nf], aPh, vl0, vl1);
                mma16(o[nf], aPl, vh0, vh1);
            }
        }
        __syncthreads();
    }

    float iA = 1.0f / lA, iB = 1.0f / lB;
    #pragma unroll
    for (int nf = 0; nf < 8; nf++) {
        int col = h*64 + nf*8 + 2*tig;
        uint32_t h0, l0, h1, l1;
        split2(o[nf][0]*iA, o[nf][1]*iA, h0, l0);
        split2(o[nf][2]*iB, o[nf][3]*iB, h1, l1);
        size_t iAa = (rowg * HDIM + col) >> 1;
        size_t iBb = ((rowg + 8) * HDIM + col) >> 1;
        ((uint32_t*)aoh)[iAa] = h0; ((uint32_t*)aol)[iAa] = l0;
        ((uint32_t*)aoh)[iBb] = h1; ((uint32_t*)aol)[iBb] = l1;
    }
}

// ---------------------------------------------------------------------------
extern "C" void kernel_launch(void* const* d_in, const int* in_sizes, int n_in,
                              void* d_out, int out_size)
{
    const float* x     = (const float*)d_in[0];
    const float* Wq    = (const float*)d_in[1];
    const float* Wk    = (const float*)d_in[2];
    const float* Wv    = (const float*)d_in[3];
    const float* Wo    = (const float*)d_in[4];
    const float* bo    = (const float*)d_in[5];
    const float* gamma = (const float*)d_in[6];
    const float* beta  = (const float*)d_in[7];
    float* out = (float*)d_out;

    bf16 *xnh, *xnl, *qh, *ql, *kh, *kl, *vh, *vl, *aoh, *aol, *wh, *wl;
    cudaGetSymbolAddress((void**)&xnh, g_xnh); cudaGetSymbolAddress((void**)&xnl, g_xnl);
    cudaGetSymbolAddress((void**)&qh,  g_qh);  cudaGetSymbolAddress((void**)&ql,  g_ql);
    cudaGetSymbolAddress((void**)&kh,  g_kh);  cudaGetSymbolAddress((void**)&kl,  g_kl);
    cudaGetSymbolAddress((void**)&vh,  g_vh);  cudaGetSymbolAddress((void**)&vl,  g_vl);
    cudaGetSymbolAddress((void**)&aoh, g_aoh); cudaGetSymbolAddress((void**)&aol, g_aol);
    cudaGetSymbolAddress((void**)&wh,  g_wh);  cudaGetSymbolAddress((void**)&wl,  g_wl);

    cudaFuncSetAttribute(attn_bf, cudaFuncAttributeMaxDynamicSharedMemorySize, ATT_SMEM);

    // 0. split weights into bf16 hi/lo
    const int SB = WSZ / 4 / 256;   // 1024 blocks per matrix
    split_arr<<<SB, 256>>>(Wq, wh + 0*WSZ, wl + 0*WSZ);
    split_arr<<<SB, 256>>>(Wk, wh + 1*WSZ, wl + 1*WSZ);
    split_arr<<<SB, 256>>>(Wv, wh + 2*WSZ, wl + 2*WSZ);
    split_arr<<<SB, 256>>>(Wo, wh + 3*WSZ, wl + 3*WSZ);

    // 1. LayerNorm -> xn hi/lo
    ln_kernel<<<MROWS, 256>>>(x, gamma, beta, xnh, xnl);

    // 2. Fused QKV projections (z selects weight + outputs)
    dim3 ggrid(HDIM / 128, MROWS / 128, 3);
    gemm_bf3<0><<<ggrid, 256>>>(xnh, xnl, wh, wl,
                                qh, ql, kh, kl, vh, vl,
                                nullptr, nullptr, nullptr);

    // 3. Flash attention
    dim3 agrid(SEQ / 128, BATCH * NH);
    attn_bf<<<agrid, 256, ATT_SMEM>>>(qh, ql, kh, kl, vh, vl, aoh, aol);

    // 4. Output projection + bias + residual (fp32 out)
    dim3 ogrid(HDIM / 128, MROWS / 128, 1);
    gemm_bf3<1><<<ogrid, 256>>>(aoh, aol, wh + 3*WSZ, wl + 3*WSZ,
                                nullptr, nullptr, nullptr, nullptr, nullptr, nullptr,
                                out, bo, x);
}

// round 10
// speedup vs baseline: 2.9833x; 1.1668x over previous
#include <cuda_runtime.h>
#include <cuda_bf16.h>
#include <math.h>
#include <stdint.h>

#define HDIM 1024
#define NH 16
#define HD 64
#define BATCH 2
#define SEQ 2048
#define MROWS (BATCH*SEQ)   // 4096
#define LN_EPS 1e-5f
#define WSZ (HDIM*HDIM)

typedef __nv_bfloat16 bf16;

// ---------------- scratch (allocation-free rule: __device__ globals) --------
__device__ bf16 g_xnh[MROWS*HDIM], g_xnl[MROWS*HDIM];
__device__ bf16 g_qh [MROWS*HDIM], g_ql [MROWS*HDIM];
__device__ bf16 g_kh [MROWS*HDIM], g_kl [MROWS*HDIM];
__device__ bf16 g_vh [MROWS*HDIM], g_vl [MROWS*HDIM];
__device__ bf16 g_aoh[MROWS*HDIM], g_aol[MROWS*HDIM];
__device__ bf16 g_wh[4*WSZ], g_wl[4*WSZ];

// ---------------- helpers ---------------------------------------------------
__device__ __forceinline__ uint32_t packbf(float a, float b) {
    __nv_bfloat162 t = __floats2bfloat162_rn(a, b);
    return *reinterpret_cast<uint32_t*>(&t);
}
__device__ __forceinline__ void split2(float a, float b, uint32_t& hi, uint32_t& lo) {
    float ha = __bfloat162float(__float2bfloat16_rn(a));
    float hb = __bfloat162float(__float2bfloat16_rn(b));
    hi = packbf(ha, hb);
    lo = packbf(a - ha, b - hb);
}
__device__ __forceinline__ void mma16(float* d, const uint32_t* a, uint32_t b0, uint32_t b1) {
    asm volatile(
        "mma.sync.aligned.m16n8k16.row.col.f32.bf16.bf16.f32 "
        "{%0,%1,%2,%3},{%4,%5,%6,%7},{%8,%9},{%0,%1,%2,%3};"
        : "+f"(d[0]), "+f"(d[1]), "+f"(d[2]), "+f"(d[3])
        : "r"(a[0]), "r"(a[1]), "r"(a[2]), "r"(a[3]), "r"(b0), "r"(b1));
}
__device__ __forceinline__ uint32_t smem_u32(const void* p) {
    return (uint32_t)__cvta_generic_to_shared(p);
}
__device__ __forceinline__ void cpa16(uint32_t s, const void* g) {
    asm volatile("cp.async.cg.shared.global [%0], [%1], 16;" :: "r"(s), "l"(g));
}
__device__ __forceinline__ void ldsm_x4(uint32_t* r, uint32_t addr) {
    asm volatile("ldmatrix.sync.aligned.m8n8.x4.shared.b16 {%0,%1,%2,%3},[%4];"
                 : "=r"(r[0]), "=r"(r[1]), "=r"(r[2]), "=r"(r[3]) : "r"(addr));
}
__device__ __forceinline__ void ldsm_x4_t(uint32_t* r, uint32_t addr) {
    asm volatile("ldmatrix.sync.aligned.m8n8.x4.trans.shared.b16 {%0,%1,%2,%3},[%4];"
                 : "=r"(r[0]), "=r"(r[1]), "=r"(r[2]), "=r"(r[3]) : "r"(addr));
}
#define CP_COMMIT asm volatile("cp.async.commit_group;")
#define CP_WAIT0  asm volatile("cp.async.wait_group 0;")
#define CP_WAIT1  asm volatile("cp.async.wait_group 1;")

// ---------------- weight split: fp32 -> bf16 hi/lo --------------------------
__global__ void split_arr(const float* __restrict__ src, bf16* __restrict__ h,
                          bf16* __restrict__ l)
{
    int i = blockIdx.x * 256 + threadIdx.x;
    float4 v = ((const float4*)src)[i];
    uint32_t h0, l0, h1, l1;
    split2(v.x, v.y, h0, l0);
    split2(v.z, v.w, h1, l1);
    ((uint32_t*)h)[2*i]   = h0; ((uint32_t*)h)[2*i+1] = h1;
    ((uint32_t*)l)[2*i]   = l0; ((uint32_t*)l)[2*i+1] = l1;
}

// ---------------- LayerNorm -> bf16 hi/lo -----------------------------------
__global__ void ln_kernel(const float* __restrict__ x,
                          const float* __restrict__ gamma,
                          const float* __restrict__ beta,
                          bf16* __restrict__ xnh, bf16* __restrict__ xnl)
{
    int row = blockIdx.x;
    int tid = threadIdx.x;
    const float4* xr = (const float4*)(x + (size_t)row * HDIM);
    float4 v = xr[tid];
    float s  = v.x + v.y + v.z + v.w;
    float ss = v.x*v.x + v.y*v.y + v.z*v.z + v.w*v.w;
    #pragma unroll
    for (int o = 16; o; o >>= 1) {
        s  += __shfl_xor_sync(0xffffffffu, s,  o);
        ss += __shfl_xor_sync(0xffffffffu, ss, o);
    }
    __shared__ float red0[8], red1[8];
    int w = tid >> 5, l = tid & 31;
    if (l == 0) { red0[w] = s; red1[w] = ss; }
    __syncthreads();
    float ts = 0.f, tss = 0.f;
    #pragma unroll
    for (int i = 0; i < 8; i++) { ts += red0[i]; tss += red1[i]; }
    float mu  = ts * (1.0f / HDIM);
    float var = tss * (1.0f / HDIM) - mu * mu;
    float inv = rsqrtf(var + LN_EPS);

    float4 g = ((const float4*)gamma)[tid];
    float4 b = ((const float4*)beta)[tid];
    float o0 = (v.x - mu) * inv * g.x + b.x;
    float o1 = (v.y - mu) * inv * g.y + b.y;
    float o2 = (v.z - mu) * inv * g.z + b.z;
    float o3 = (v.w - mu) * inv * g.w + b.w;
    uint32_t h0, l0, h1, l1;
    split2(o0, o1, h0, l0);
    split2(o2, o3, h1, l1);
    uint32_t base = row * (HDIM/2) + tid * 2;
    ((uint32_t*)xnh)[base]   = h0; ((uint32_t*)xnh)[base+1] = h1;
    ((uint32_t*)xnl)[base]   = l0; ((uint32_t*)xnl)[base+1] = l1;
}

// ---------------- 3-term bf16 NT GEMM (ldmatrix operand feed) ----------------
// C[M,N] = (Ah+Al) * (Wh+Wl)^T, fp32 accum.  BM=BN=128, BK=16, 256 thr
// (8 warps 2x4), warp tile 64x32.  cp.async double buffer; all fragments via
// ldmatrix.x4.  FINAL=0: epilogue re-splits C to bf16 hi/lo; FINAL=1: fp32
// C = acc + bias + resid.
template <int FINAL>
__global__ void __launch_bounds__(256, 2)
gemm_bf3(const bf16* __restrict__ Ah, const bf16* __restrict__ Al,
         const bf16* __restrict__ Wh0, const bf16* __restrict__ Wl0,
         bf16* C0h, bf16* C0l, bf16* C1h, bf16* C1l, bf16* C2h, bf16* C2l,
         float* __restrict__ Cf, const float* __restrict__ bias,
         const float* __restrict__ resid)
{
    const int SA = 24;   // padded row stride (bf16)
    __shared__ bf16 sAh[2][128*SA], sAl[2][128*SA];
    __shared__ bf16 sBh[2][128*SA], sBl[2][128*SA];

    int z = blockIdx.z;
    const bf16* Wh = Wh0 + (size_t)z * WSZ;
    const bf16* Wl = Wl0 + (size_t)z * WSZ;
    bf16* Ch = (z == 0) ? C0h : (z == 1 ? C1h : C2h);
    bf16* Cl = (z == 0) ? C0l : (z == 1 ? C1l : C2l);

    int tid  = threadIdx.x;
    int m0   = blockIdx.y * 128;
    int n0   = blockIdx.x * 128;
    int w    = tid >> 5, lane = tid & 31;
    int gid  = lane >> 2, tig = lane & 3;
    int wr   = w >> 2, wc = w & 3;

    float acc[4][4][4];
    #pragma unroll
    for (int i = 0; i < 4; i++)
        #pragma unroll
        for (int j = 0; j < 4; j++)
            #pragma unroll
            for (int e = 0; e < 4; e++) acc[i][j][e] = 0.f;

    // ldmatrix per-lane source rows/cols
    int rowA = (lane & 7) + ((lane >> 3) & 1) * 8;   // a0(m0-7,k0-7) a1(m8-15,k0-7) a2(..k8-15) a3
    int colA = ((lane >> 4) & 1) * 8;
    int rowB = (lane & 7) + ((lane >> 4) & 1) * 8;   // b: m0(n0-7,k0-7) m1(n0-7,k8-15) m2(n8,k0) m3(n8,k8)
    int colB = ((lane >> 3) & 1) * 8;

    uint32_t offA[4], offB[2];
    #pragma unroll
    for (int mf = 0; mf < 4; mf++)
        offA[mf] = ((wr*64 + mf*16 + rowA) * SA + colA) * 2;
    #pragma unroll
    for (int p = 0; p < 2; p++)
        offB[p] = ((wc*32 + p*16 + rowB) * SA + colB) * 2;

    uint32_t bAh[2] = { smem_u32(&sAh[0][0]), smem_u32(&sAh[1][0]) };
    uint32_t bAl[2] = { smem_u32(&sAl[0][0]), smem_u32(&sAl[1][0]) };
    uint32_t bBh[2] = { smem_u32(&sBh[0][0]), smem_u32(&sBh[1][0]) };
    uint32_t bBl[2] = { smem_u32(&sBl[0][0]), smem_u32(&sBl[1][0]) };

    int lrow = tid >> 1;              // 0..127
    int lofs = (tid & 1) * 8;         // 0 or 8
    auto issue = [&](int stage, int k0) {
        uint32_t d0 = smem_u32(&sAh[stage][lrow*SA + lofs]);
        uint32_t d1 = smem_u32(&sAl[stage][lrow*SA + lofs]);
        uint32_t d2 = smem_u32(&sBh[stage][lrow*SA + lofs]);
        uint32_t d3 = smem_u32(&sBl[stage][lrow*SA + lofs]);
        size_t ma = (size_t)(m0 + lrow) * HDIM + k0 + lofs;
        size_t nb = (size_t)(n0 + lrow) * HDIM + k0 + lofs;
        cpa16(d0, Ah + ma);
        cpa16(d1, Al + ma);
        cpa16(d2, Wh + nb);
        cpa16(d3, Wl + nb);
        CP_COMMIT;
    };

    issue(0, 0);
    const int NC = HDIM / 16;
    for (int c = 0; c < NC; c++) {
        int buf = c & 1;
        if (c + 1 < NC) { issue(buf ^ 1, (c + 1) * 16); CP_WAIT1; }
        else            { CP_WAIT0; }
        __syncthreads();

        uint32_t bh[2][4], bl[2][4];
        #pragma unroll
        for (int p = 0; p < 2; p++) {
            ldsm_x4(bh[p], bBh[buf] + offB[p]);
            ldsm_x4(bl[p], bBl[buf] + offB[p]);
        }
        #pragma unroll
        for (int mf = 0; mf < 4; mf++) {
            uint32_t ah[4], al[4];
            ldsm_x4(ah, bAh[buf] + offA[mf]);
            ldsm_x4(al, bAl[buf] + offA[mf]);
            #pragma unroll
            for (int p = 0; p < 2; p++) {
                mma16(acc[mf][2*p],   ah, bh[p][0], bh[p][1]);
                mma16(acc[mf][2*p+1], ah, bh[p][2], bh[p][3]);
                mma16(acc[mf][2*p],   ah, bl[p][0], bl[p][1]);
                mma16(acc[mf][2*p+1], ah, bl[p][2], bl[p][3]);
                mma16(acc[mf][2*p],   al, bh[p][0], bh[p][1]);
                mma16(acc[mf][2*p+1], al, bh[p][2], bh[p][3]);
            }
        }
        __syncthreads();
    }

    #pragma unroll
    for (int mf = 0; mf < 4; mf++) {
        int r0 = m0 + wr*64 + mf*16 + gid;
        #pragma unroll
        for (int nf = 0; nf < 4; nf++) {
            int col = n0 + wc*32 + nf*8 + 2*tig;
            if (FINAL) {
                float2 bi = *(const float2*)(bias + col);
                float2 rA = *(const float2*)(resid + (size_t)r0 * HDIM + col);
                float2 rB = *(const float2*)(resid + (size_t)(r0+8) * HDIM + col);
                *(float2*)(Cf + (size_t)r0 * HDIM + col) =
                    make_float2(acc[mf][nf][0] + bi.x + rA.x, acc[mf][nf][1] + bi.y + rA.y);
                *(float2*)(Cf + (size_t)(r0+8) * HDIM + col) =
                    make_float2(acc[mf][nf][2] + bi.x + rB.x, acc[mf][nf][3] + bi.y + rB.y);
            } else {
                uint32_t h0, l0, h1, l1;
                split2(acc[mf][nf][0], acc[mf][nf][1], h0, l0);
                split2(acc[mf][nf][2], acc[mf][nf][3], h1, l1);
                size_t iA = ((size_t)r0 * HDIM + col) >> 1;
                size_t iB = ((size_t)(r0+8) * HDIM + col) >> 1;
                ((uint32_t*)Ch)[iA] = h0; ((uint32_t*)Cl)[iA] = l0;
                ((uint32_t*)Ch)[iB] = h1; ((uint32_t*)Cl)[iB] = l1;
            }
        }
    }
}

// ---------------- flash attention, 3-term bf16, ldmatrix feeds --------------
#define ATT_S 72
#define ATT_ARR (64*ATT_S)
#define ATT_STAGE (4*ATT_ARR)
#define ATT_SMEM (2*ATT_STAGE*2)

__global__ void __launch_bounds__(256)
attn_bf(const bf16* __restrict__ qh, const bf16* __restrict__ ql,
        const bf16* __restrict__ kh, const bf16* __restrict__ kl,
        const bf16* __restrict__ vh, const bf16* __restrict__ vl,
        bf16* __restrict__ aoh, bf16* __restrict__ aol)
{
    extern __shared__ bf16 sm[];

    int tid = threadIdx.x, w = tid >> 5, lane = tid & 31;
    int gid = lane >> 2, tig = lane & 3;
    int bh = blockIdx.y, b = bh >> 4, h = bh & 15;
    int q0 = blockIdx.x * 128;

    size_t rowg = (size_t)b * SEQ + q0 + w*16 + gid;

    uint32_t qfh[4][4], qfl[4][4];
    #pragma unroll
    for (int kg = 0; kg < 4; kg++) {
        int cb = h*64 + kg*16 + 2*tig;
        size_t i00 = rowg * HDIM + cb;
        size_t i10 = (rowg + 8) * HDIM + cb;
        qfh[kg][0] = *(const uint32_t*)&qh[i00];
        qfh[kg][1] = *(const uint32_t*)&qh[i10];
        qfh[kg][2] = *(const uint32_t*)&qh[i00 + 8];
        qfh[kg][3] = *(const uint32_t*)&qh[i10 + 8];
        qfl[kg][0] = *(const uint32_t*)&ql[i00];
        qfl[kg][1] = *(const uint32_t*)&ql[i10];
        qfl[kg][2] = *(const uint32_t*)&ql[i00 + 8];
        qfl[kg][3] = *(const uint32_t*)&ql[i10 + 8];
    }

    // ldmatrix per-lane offsets
    int rowK = (lane & 7) + ((lane >> 4) & 1) * 8;   // B-type (key rows)
    int colK = ((lane >> 3) & 1) * 8;
    uint32_t loffK = (rowK * ATT_S + colK) * 2;
    int rowV = (lane & 7) + ((lane >> 3) & 1) * 8;   // trans source (k rows)
    int colV = ((lane >> 4) & 1) * 8;
    uint32_t loffV = (rowV * ATT_S + colV) * 2;

    float o[8][4];
    #pragma unroll
    for (int nf = 0; nf < 8; nf++)
        #pragma unroll
        for (int e = 0; e < 4; e++) o[nf][e] = 0.f;
    float mA = -1e30f, mB = -1e30f, lA = 0.f, lB = 0.f;

    const bf16* srcs[4] = { kh, kl, vh, vl };
    auto load_tile = [&](int stage, int t) {
        #pragma unroll
        for (int i = 0; i < 8; i++) {
            int ch  = i * 256 + tid;
            int arr = ch >> 9;
            int r   = (ch >> 3) & 63;
            int c8  = (ch & 7) * 8;
            const bf16* src = srcs[arr] +
                ((size_t)b * SEQ + t*64 + r) * HDIM + h*64 + c8;
            cpa16(smem_u32(&sm[stage*ATT_STAGE + arr*ATT_ARR + r*ATT_S + c8]), src);
        }
        CP_COMMIT;
    };

    load_tile(0, 0);
    const int NT = SEQ / 64;
    for (int t = 0; t < NT; t++) {
        int buf = t & 1;
        if (t + 1 < NT) { load_tile(buf ^ 1, t + 1); CP_WAIT1; }
        else            { CP_WAIT0; }
        __syncthreads();

        uint32_t Khb = smem_u32(sm + buf*ATT_STAGE);
        uint32_t Klb = Khb + ATT_ARR*2;
        uint32_t Vhb = Khb + 2*ATT_ARR*2;
        uint32_t Vlb = Khb + 3*ATT_ARR*2;

        float s[8][4];
        #pragma unroll
        for (int nf = 0; nf < 8; nf++)
            #pragma unroll
            for (int e = 0; e < 4; e++) s[nf][e] = 0.f;

        #pragma unroll
        for (int kg = 0; kg < 4; kg++) {
            #pragma unroll
            for (int p = 0; p < 4; p++) {
                uint32_t koff = (uint32_t)((p*16*ATT_S + kg*16) * 2) + loffK;
                uint32_t kh4[4], kl4[4];
                ldsm_x4(kh4, Khb + koff);
                ldsm_x4(kl4, Klb + koff);
                mma16(s[2*p],   qfh[kg], kh4[0], kh4[1]);
                mma16(s[2*p+1], qfh[kg], kh4[2], kh4[3]);
                mma16(s[2*p],   qfh[kg], kl4[0], kl4[1]);
                mma16(s[2*p+1], qfh[kg], kl4[2], kl4[3]);
                mma16(s[2*p],   qfl[kg], kh4[0], kh4[1]);
                mma16(s[2*p+1], qfl[kg], kh4[2], kh4[3]);
            }
        }

        #pragma unroll
        for (int nf = 0; nf < 8; nf++)
            #pragma unroll
            for (int e = 0; e < 4; e++) s[nf][e] *= 0.125f;

        float mxA = -1e30f, mxB = -1e30f;
        #pragma unroll
        for (int nf = 0; nf < 8; nf++) {
            mxA = fmaxf(mxA, fmaxf(s[nf][0], s[nf][1]));
            mxB = fmaxf(mxB, fmaxf(s[nf][2], s[nf][3]));
        }
        #pragma unroll
        for (int ofs = 1; ofs <= 2; ofs <<= 1) {
            mxA = fmaxf(mxA, __shfl_xor_sync(0xffffffffu, mxA, ofs));
            mxB = fmaxf(mxB, __shfl_xor_sync(0xffffffffu, mxB, ofs));
        }
        float mnA = fmaxf(mA, mxA), mnB = fmaxf(mB, mxB);
        float alpA = __expf(mA - mnA), alpB = __expf(mB - mnB);
        mA = mnA; mB = mnB;

        float rsA = 0.f, rsB = 0.f;
        #pragma unroll
        for (int nf = 0; nf < 8; nf++) {
            s[nf][0] = __expf(s[nf][0] - mnA);
            s[nf][1] = __expf(s[nf][1] - mnA);
            s[nf][2] = __expf(s[nf][2] - mnB);
            s[nf][3] = __expf(s[nf][3] - mnB);
            rsA += s[nf][0] + s[nf][1];
            rsB += s[nf][2] + s[nf][3];
        }
        #pragma unroll
        for (int ofs = 1; ofs <= 2; ofs <<= 1) {
            rsA += __shfl_xor_sync(0xffffffffu, rsA, ofs);
            rsB += __shfl_xor_sync(0xffffffffu, rsB, ofs);
        }
        lA = lA * alpA + rsA;
        lB = lB * alpB + rsB;
        #pragma unroll
        for (int nf = 0; nf < 8; nf++) {
            o[nf][0] *= alpA; o[nf][1] *= alpA;
            o[nf][2] *= alpB; o[nf][3] *= alpB;
        }

        #pragma unroll
        for (int kg = 0; kg < 4; kg++) {
            uint32_t aPh[4], aPl[4];
            split2(s[2*kg][0],   s[2*kg][1],   aPh[0], aPl[0]);
            split2(s[2*kg][2],   s[2*kg][3],   aPh[1], aPl[1]);
            split2(s[2*kg+1][0], s[2*kg+1][1], aPh[2], aPl[2]);
            split2(s[2*kg+1][2], s[2*kg+1][3], aPh[3], aPl[3]);
            #pragma unroll
            for (int p = 0; p < 4; p++) {
                uint32_t voff = (uint32_t)((kg*16*ATT_S + p*16) * 2) + loffV;
                uint32_t vh4[4], vl4[4];
                ldsm_x4_t(vh4, Vhb + voff);
                ldsm_x4_t(vl4, Vlb + voff);
                mma16(o[2*p],   aPh, vh4[0], vh4[1]);
                mma16(o[2*p+1], aPh, vh4[2], vh4[3]);
                mma16(o[2*p],   aPh, vl4[0], vl4[1]);
                mma16(o[2*p+1], aPh, vl4[2], vl4[3]);
                mma16(o[2*p],   aPl, vh4[0], vh4[1]);
                mma16(o[2*p+1], aPl, vh4[2], vh4[3]);
            }
        }
        __syncthreads();
    }

    float iA = 1.0f / lA, iB = 1.0f / lB;
    #pragma unroll
    for (int nf = 0; nf < 8; nf++) {
        int col = h*64 + nf*8 + 2*tig;
        uint32_t h0, l0, h1, l1;
        split2(o[nf][0]*iA, o[nf][1]*iA, h0, l0);
        split2(o[nf][2]*iB, o[nf][3]*iB, h1, l1);
        size_t iAa = (rowg * HDIM + col) >> 1;
        size_t iBb = ((rowg + 8) * HDIM + col) >> 1;
        ((uint32_t*)aoh)[iAa] = h0; ((uint32_t*)aol)[iAa] = l0;
        ((uint32_t*)aoh)[iBb] = h1; ((uint32_t*)aol)[iBb] = l1;
    }
}

// ---------------------------------------------------------------------------
extern "C" void kernel_launch(void* const* d_in, const int* in_sizes, int n_in,
                              void* d_out, int out_size)
{
    const float* x     = (const float*)d_in[0];
    const float* Wq    = (const float*)d_in[1];
    const float* Wk    = (const float*)d_in[2];
    const float* Wv    = (const float*)d_in[3];
    const float* Wo    = (const float*)d_in[4];
    const float* bo    = (const float*)d_in[5];
    const float* gamma = (const float*)d_in[6];
    const float* beta  = (const float*)d_in[7];
    float* out = (float*)d_out;

    bf16 *xnh, *xnl, *qh, *ql, *kh, *kl, *vh, *vl, *aoh, *aol, *wh, *wl;
    cudaGetSymbolAddress((void**)&xnh, g_xnh); cudaGetSymbolAddress((void**)&xnl, g_xnl);
    cudaGetSymbolAddress((void**)&qh,  g_qh);  cudaGetSymbolAddress((void**)&ql,  g_ql);
    cudaGetSymbolAddress((void**)&kh,  g_kh);  cudaGetSymbolAddress((void**)&kl,  g_kl);
    cudaGetSymbolAddress((void**)&vh,  g_vh);  cudaGetSymbolAddress((void**)&vl,  g_vl);
    cudaGetSymbolAddress((void**)&aoh, g_aoh); cudaGetSymbolAddress((void**)&aol, g_aol);
    cudaGetSymbolAddress((void**)&wh,  g_wh);  cudaGetSymbolAddress((void**)&wl,  g_wl);

    cudaFuncSetAttribute(attn_bf, cudaFuncAttributeMaxDynamicSharedMemorySize, ATT_SMEM);

    // 0. split weights into bf16 hi/lo
    const int SB = WSZ / 4 / 256;
    split_arr<<<SB, 256>>>(Wq, wh + 0*WSZ, wl + 0*WSZ);
    split_arr<<<SB, 256>>>(Wk, wh + 1*WSZ, wl + 1*WSZ);
    split_arr<<<SB, 256>>>(Wv, wh + 2*WSZ, wl + 2*WSZ);
    split_arr<<<SB, 256>>>(Wo, wh + 3*WSZ, wl + 3*WSZ);

    // 1. LayerNorm -> xn hi/lo
    ln_kernel<<<MROWS, 256>>>(x, gamma, beta, xnh, xnl);

    // 2. Fused QKV projections
    dim3 ggrid(HDIM / 128, MROWS / 128, 3);
    gemm_bf3<0><<<ggrid, 256>>>(xnh, xnl, wh, wl,
                                qh, ql, kh, kl, vh, vl,
                                nullptr, nullptr, nullptr);

    // 3. Flash attention
    dim3 agrid(SEQ / 128, BATCH * NH);
    attn_bf<<<agrid, 256, ATT_SMEM>>>(qh, ql, kh, kl, vh, vl, aoh, aol);

    // 4. Output projection + bias + residual
    dim3 ogrid(HDIM / 128, MROWS / 128, 1);
    gemm_bf3<1><<<ogrid, 256>>>(aoh, aol, wh + 3*WSZ, wl + 3*WSZ,
                                nullptr, nullptr, nullptr, nullptr, nullptr, nullptr,
                                out, bo, x);
}

// round 11
// speedup vs baseline: 4.3475x; 1.4573x over previous
#include <cuda_runtime.h>
#include <cuda_fp16.h>
#include <math.h>
#include <stdint.h>

#define HDIM 1024
#define NH 16
#define HD 64
#define BATCH 2
#define SEQ 2048
#define MROWS (BATCH*SEQ)   // 4096
#define LN_EPS 1e-5f
#define WSZ (HDIM*HDIM)

typedef __half half_t;

// ---------------- scratch (allocation-free rule: __device__ globals) --------
__device__ half_t g_xn[MROWS*HDIM];
__device__ half_t g_q [MROWS*HDIM];
__device__ half_t g_k [MROWS*HDIM];
__device__ half_t g_v [MROWS*HDIM];
__device__ half_t g_ao[MROWS*HDIM];
__device__ half_t g_w [4*WSZ];

// ---------------- helpers ---------------------------------------------------
__device__ __forceinline__ uint32_t pack2h(float a, float b) {
    __half2 t = __floats2half2_rn(a, b);
    return *reinterpret_cast<uint32_t*>(&t);
}
__device__ __forceinline__ void mma16(float* d, const uint32_t* a, uint32_t b0, uint32_t b1) {
    asm volatile(
        "mma.sync.aligned.m16n8k16.row.col.f32.f16.f16.f32 "
        "{%0,%1,%2,%3},{%4,%5,%6,%7},{%8,%9},{%0,%1,%2,%3};"
        : "+f"(d[0]), "+f"(d[1]), "+f"(d[2]), "+f"(d[3])
        : "r"(a[0]), "r"(a[1]), "r"(a[2]), "r"(a[3]), "r"(b0), "r"(b1));
}
__device__ __forceinline__ uint32_t smem_u32(const void* p) {
    return (uint32_t)__cvta_generic_to_shared(p);
}
__device__ __forceinline__ void cpa16(uint32_t s, const void* g) {
    asm volatile("cp.async.cg.shared.global [%0], [%1], 16;" :: "r"(s), "l"(g));
}
__device__ __forceinline__ void ldsm_x4(uint32_t* r, uint32_t addr) {
    asm volatile("ldmatrix.sync.aligned.m8n8.x4.shared.b16 {%0,%1,%2,%3},[%4];"
                 : "=r"(r[0]), "=r"(r[1]), "=r"(r[2]), "=r"(r[3]) : "r"(addr));
}
__device__ __forceinline__ void ldsm_x4_t(uint32_t* r, uint32_t addr) {
    asm volatile("ldmatrix.sync.aligned.m8n8.x4.trans.shared.b16 {%0,%1,%2,%3},[%4];"
                 : "=r"(r[0]), "=r"(r[1]), "=r"(r[2]), "=r"(r[3]) : "r"(addr));
}
#define CP_COMMIT asm volatile("cp.async.commit_group;")
#define CP_WAIT0  asm volatile("cp.async.wait_group 0;")
#define CP_WAIT1  asm volatile("cp.async.wait_group 1;")

// ---------------- weight convert: fp32 -> fp16 -------------------------------
__global__ void cvt_arr(const float* __restrict__ src, half_t* __restrict__ dst)
{
    int i = blockIdx.x * 256 + threadIdx.x;
    float4 v = ((const float4*)src)[i];
    ((uint32_t*)dst)[2*i]   = pack2h(v.x, v.y);
    ((uint32_t*)dst)[2*i+1] = pack2h(v.z, v.w);
}

// ---------------- LayerNorm -> fp16 ------------------------------------------
__global__ void ln_kernel(const float* __restrict__ x,
                          const float* __restrict__ gamma,
                          const float* __restrict__ beta,
                          half_t* __restrict__ xn)
{
    int row = blockIdx.x;
    int tid = threadIdx.x;
    const float4* xr = (const float4*)(x + (size_t)row * HDIM);
    float4 v = xr[tid];
    float s  = v.x + v.y + v.z + v.w;
    float ss = v.x*v.x + v.y*v.y + v.z*v.z + v.w*v.w;
    #pragma unroll
    for (int o = 16; o; o >>= 1) {
        s  += __shfl_xor_sync(0xffffffffu, s,  o);
        ss += __shfl_xor_sync(0xffffffffu, ss, o);
    }
    __shared__ float red0[8], red1[8];
    int w = tid >> 5, l = tid & 31;
    if (l == 0) { red0[w] = s; red1[w] = ss; }
    __syncthreads();
    float ts = 0.f, tss = 0.f;
    #pragma unroll
    for (int i = 0; i < 8; i++) { ts += red0[i]; tss += red1[i]; }
    float mu  = ts * (1.0f / HDIM);
    float var = tss * (1.0f / HDIM) - mu * mu;
    float inv = rsqrtf(var + LN_EPS);

    float4 g = ((const float4*)gamma)[tid];
    float4 b = ((const float4*)beta)[tid];
    float o0 = (v.x - mu) * inv * g.x + b.x;
    float o1 = (v.y - mu) * inv * g.y + b.y;
    float o2 = (v.z - mu) * inv * g.z + b.z;
    float o3 = (v.w - mu) * inv * g.w + b.w;
    uint32_t base = row * (HDIM/2) + tid * 2;
    ((uint32_t*)xn)[base]   = pack2h(o0, o1);
    ((uint32_t*)xn)[base+1] = pack2h(o2, o3);
}

// ---------------- fp16 NT GEMM ------------------------------------------------
// C[M,N] = A[M,K] * W[N,K]^T, fp32 accum.  BM=BN=128, BK=32, 256 thr (8 warps
// 2x4), warp tile 64x32.  cp.async double buffer, ldmatrix.x4 operand feed.
// FINAL=0: fp16 C out (z selects W and C for fused QKV); FINAL=1: fp32
// C = acc + bias + resid.
template <int FINAL>
__global__ void __launch_bounds__(256, 2)
gemm_hf(const half_t* __restrict__ A, const half_t* __restrict__ W0,
        half_t* C0, half_t* C1, half_t* C2,
        float* __restrict__ Cf, const float* __restrict__ bias,
        const float* __restrict__ resid)
{
    const int SA = 40;   // padded row stride (halfs) for BK=32
    __shared__ half_t sA[2][128*SA];
    __shared__ half_t sB[2][128*SA];

    int z = blockIdx.z;
    const half_t* W = W0 + (size_t)z * WSZ;
    half_t* C = (z == 0) ? C0 : (z == 1 ? C1 : C2);

    int tid  = threadIdx.x;
    int m0   = blockIdx.y * 128;
    int n0   = blockIdx.x * 128;
    int w    = tid >> 5, lane = tid & 31;
    int gid  = lane >> 2, tig = lane & 3;
    int wr   = w >> 2, wc = w & 3;

    float acc[4][4][4];
    #pragma unroll
    for (int i = 0; i < 4; i++)
        #pragma unroll
        for (int j = 0; j < 4; j++)
            #pragma unroll
            for (int e = 0; e < 4; e++) acc[i][j][e] = 0.f;

    int rowA = (lane & 7) + ((lane >> 3) & 1) * 8;
    int colA = ((lane >> 4) & 1) * 8;
    int rowB = (lane & 7) + ((lane >> 4) & 1) * 8;
    int colB = ((lane >> 3) & 1) * 8;

    uint32_t offA[4], offB[2];
    #pragma unroll
    for (int mf = 0; mf < 4; mf++)
        offA[mf] = ((wr*64 + mf*16 + rowA) * SA + colA) * 2;
    #pragma unroll
    for (int p = 0; p < 2; p++)
        offB[p] = ((wc*32 + p*16 + rowB) * SA + colB) * 2;

    uint32_t bA[2] = { smem_u32(&sA[0][0]), smem_u32(&sA[1][0]) };
    uint32_t bB[2] = { smem_u32(&sB[0][0]), smem_u32(&sB[1][0]) };

    auto issue = [&](int stage, int k0) {
        #pragma unroll
        for (int i = 0; i < 2; i++) {
            int ch  = tid * 2 + i;            // 0..511
            int row = ch >> 2, off = (ch & 3) * 8;
            cpa16(smem_u32(&sA[stage][row*SA + off]),
                  A + (size_t)(m0 + row) * HDIM + k0 + off);
            cpa16(smem_u32(&sB[stage][row*SA + off]),
                  W + (size_t)(n0 + row) * HDIM + k0 + off);
        }
        CP_COMMIT;
    };

    issue(0, 0);
    const int NC = HDIM / 32;                 // 32 chunks
    for (int c = 0; c < NC; c++) {
        int buf = c & 1;
        if (c + 1 < NC) { issue(buf ^ 1, (c + 1) * 32); CP_WAIT1; }
        else            { CP_WAIT0; }
        __syncthreads();

        #pragma unroll
        for (int kg = 0; kg < 2; kg++) {
            uint32_t kgo = kg * 32;           // 16 halfs
            uint32_t bb[2][4];
            #pragma unroll
            for (int p = 0; p < 2; p++)
                ldsm_x4(bb[p], bB[buf] + offB[p] + kgo);
            #pragma unroll
            for (int mf = 0; mf < 4; mf++) {
                uint32_t a4[4];
                ldsm_x4(a4, bA[buf] + offA[mf] + kgo);
                #pragma unroll
                for (int p = 0; p < 2; p++) {
                    mma16(acc[mf][2*p],   a4, bb[p][0], bb[p][1]);
                    mma16(acc[mf][2*p+1], a4, bb[p][2], bb[p][3]);
                }
            }
        }
        __syncthreads();
    }

    #pragma unroll
    for (int mf = 0; mf < 4; mf++) {
        int r0 = m0 + wr*64 + mf*16 + gid;
        #pragma unroll
        for (int nf = 0; nf < 4; nf++) {
            int col = n0 + wc*32 + nf*8 + 2*tig;
            if (FINAL) {
                float2 bi = *(const float2*)(bias + col);
                float2 rA = *(const float2*)(resid + (size_t)r0 * HDIM + col);
                float2 rB = *(const float2*)(resid + (size_t)(r0+8) * HDIM + col);
                *(float2*)(Cf + (size_t)r0 * HDIM + col) =
                    make_float2(acc[mf][nf][0] + bi.x + rA.x, acc[mf][nf][1] + bi.y + rA.y);
                *(float2*)(Cf + (size_t)(r0+8) * HDIM + col) =
                    make_float2(acc[mf][nf][2] + bi.x + rB.x, acc[mf][nf][3] + bi.y + rB.y);
            } else {
                ((uint32_t*)C)[((size_t)r0 * HDIM + col) >> 1] =
                    pack2h(acc[mf][nf][0], acc[mf][nf][1]);
                ((uint32_t*)C)[((size_t)(r0+8) * HDIM + col) >> 1] =
                    pack2h(acc[mf][nf][2], acc[mf][nf][3]);
            }
        }
    }
}

// ---------------- flash attention, fp16 single-term ---------------------------
#define ATT_S 72
#define ATT_ARR (64*ATT_S)          // halfs per array (K or V) per stage
#define ATT_STAGE (2*ATT_ARR)

__global__ void __launch_bounds__(256)
attn_hf(const half_t* __restrict__ q, const half_t* __restrict__ k,
        const half_t* __restrict__ v, half_t* __restrict__ ao)
{
    __shared__ half_t sm[2*ATT_STAGE];      // 2 stages x (K,V) = 36 KB

    int tid = threadIdx.x, w = tid >> 5, lane = tid & 31;
    int gid = lane >> 2, tig = lane & 3;
    int bh = blockIdx.y, b = bh >> 4, h = bh & 15;
    int q0 = blockIdx.x * 128;

    size_t rowg = (size_t)b * SEQ + q0 + w*16 + gid;

    uint32_t qf[4][4];
    #pragma unroll
    for (int kg = 0; kg < 4; kg++) {
        int cb = h*64 + kg*16 + 2*tig;
        size_t i00 = rowg * HDIM + cb;
        size_t i10 = (rowg + 8) * HDIM + cb;
        qf[kg][0] = *(const uint32_t*)&q[i00];
        qf[kg][1] = *(const uint32_t*)&q[i10];
        qf[kg][2] = *(const uint32_t*)&q[i00 + 8];
        qf[kg][3] = *(const uint32_t*)&q[i10 + 8];
    }

    int rowK = (lane & 7) + ((lane >> 4) & 1) * 8;
    int colK = ((lane >> 3) & 1) * 8;
    uint32_t loffK = (rowK * ATT_S + colK) * 2;
    int rowV = (lane & 7) + ((lane >> 3) & 1) * 8;
    int colV = ((lane >> 4) & 1) * 8;
    uint32_t loffV = (rowV * ATT_S + colV) * 2;

    float o[8][4];
    #pragma unroll
    for (int nf = 0; nf < 8; nf++)
        #pragma unroll
        for (int e = 0; e < 4; e++) o[nf][e] = 0.f;
    float mA = -1e30f, mB = -1e30f, lA = 0.f, lB = 0.f;

    const half_t* srcs[2] = { k, v };
    auto load_tile = [&](int stage, int t) {
        #pragma unroll
        for (int i = 0; i < 4; i++) {
            int ch  = i * 256 + tid;          // 0..1023
            int arr = ch >> 9;
            int r   = (ch >> 3) & 63;
            int c8  = (ch & 7) * 8;
            const half_t* src = srcs[arr] +
                ((size_t)b * SEQ + t*64 + r) * HDIM + h*64 + c8;
            cpa16(smem_u32(&sm[stage*ATT_STAGE + arr*ATT_ARR + r*ATT_S + c8]), src);
        }
        CP_COMMIT;
    };

    load_tile(0, 0);
    const int NT = SEQ / 64;
    for (int t = 0; t < NT; t++) {
        int buf = t & 1;
        if (t + 1 < NT) { load_tile(buf ^ 1, t + 1); CP_WAIT1; }
        else            { CP_WAIT0; }
        __syncthreads();

        uint32_t Kb = smem_u32(sm + buf*ATT_STAGE);
        uint32_t Vb = Kb + ATT_ARR*2;

        float s[8][4];
        #pragma unroll
        for (int nf = 0; nf < 8; nf++)
            #pragma unroll
            for (int e = 0; e < 4; e++) s[nf][e] = 0.f;

        #pragma unroll
        for (int kg = 0; kg < 4; kg++) {
            #pragma unroll
            for (int p = 0; p < 4; p++) {
                uint32_t koff = (uint32_t)((p*16*ATT_S + kg*16) * 2) + loffK;
                uint32_t k4[4];
                ldsm_x4(k4, Kb + koff);
                mma16(s[2*p],   qf[kg], k4[0], k4[1]);
                mma16(s[2*p+1], qf[kg], k4[2], k4[3]);
            }
        }

        #pragma unroll
        for (int nf = 0; nf < 8; nf++)
            #pragma unroll
            for (int e = 0; e < 4; e++) s[nf][e] *= 0.125f;

        float mxA = -1e30f, mxB = -1e30f;
        #pragma unroll
        for (int nf = 0; nf < 8; nf++) {
            mxA = fmaxf(mxA, fmaxf(s[nf][0], s[nf][1]));
            mxB = fmaxf(mxB, fmaxf(s[nf][2], s[nf][3]));
        }
        #pragma unroll
        for (int ofs = 1; ofs <= 2; ofs <<= 1) {
            mxA = fmaxf(mxA, __shfl_xor_sync(0xffffffffu, mxA, ofs));
            mxB = fmaxf(mxB, __shfl_xor_sync(0xffffffffu, mxB, ofs));
        }
        float mnA = fmaxf(mA, mxA), mnB = fmaxf(mB, mxB);
        float alpA = __expf(mA - mnA), alpB = __expf(mB - mnB);
        mA = mnA; mB = mnB;

        float rsA = 0.f, rsB = 0.f;
        #pragma unroll
        for (int nf = 0; nf < 8; nf++) {
            s[nf][0] = __expf(s[nf][0] - mnA);
            s[nf][1] = __expf(s[nf][1] - mnA);
            s[nf][2] = __expf(s[nf][2] - mnB);
            s[nf][3] = __expf(s[nf][3] - mnB);
            rsA += s[nf][0] + s[nf][1];
            rsB += s[nf][2] + s[nf][3];
        }
        #pragma unroll
        for (int ofs = 1; ofs <= 2; ofs <<= 1) {
            rsA += __shfl_xor_sync(0xffffffffu, rsA, ofs);
            rsB += __shfl_xor_sync(0xffffffffu, rsB, ofs);
        }
        lA = lA * alpA + rsA;
        lB = lB * alpB + rsB;
        #pragma unroll
        for (int nf = 0; nf < 8; nf++) {
            o[nf][0] *= alpA; o[nf][1] *= alpA;
            o[nf][2] *= alpB; o[nf][3] *= alpB;
        }

        #pragma unroll
        for (int kg = 0; kg < 4; kg++) {
            uint32_t aP[4];
            aP[0] = pack2h(s[2*kg][0],   s[2*kg][1]);
            aP[1] = pack2h(s[2*kg][2],   s[2*kg][3]);
            aP[2] = pack2h(s[2*kg+1][0], s[2*kg+1][1]);
            aP[3] = pack2h(s[2*kg+1][2], s[2*kg+1][3]);
            #pragma unroll
            for (int p = 0; p < 4; p++) {
                uint32_t voff = (uint32_t)((kg*16*ATT_S + p*16) * 2) + loffV;
                uint32_t v4[4];
                ldsm_x4_t(v4, Vb + voff);
                mma16(o[2*p],   aP, v4[0], v4[1]);
                mma16(o[2*p+1], aP, v4[2], v4[3]);
            }
        }
        __syncthreads();
    }

    float iA = 1.0f / lA, iB = 1.0f / lB;
    #pragma unroll
    for (int nf = 0; nf < 8; nf++) {
        int col = h*64 + nf*8 + 2*tig;
        ((uint32_t*)ao)[(rowg * HDIM + col) >> 1] =
            pack2h(o[nf][0]*iA, o[nf][1]*iA);
        ((uint32_t*)ao)[((rowg + 8) * HDIM + col) >> 1] =
            pack2h(o[nf][2]*iB, o[nf][3]*iB);
    }
}

// ---------------------------------------------------------------------------
extern "C" void kernel_launch(void* const* d_in, const int* in_sizes, int n_in,
                              void* d_out, int out_size)
{
    const float* x     = (const float*)d_in[0];
    const float* Wq    = (const float*)d_in[1];
    const float* Wk    = (const float*)d_in[2];
    const float* Wv    = (const float*)d_in[3];
    const float* Wo    = (const float*)d_in[4];
    const float* bo    = (const float*)d_in[5];
    const float* gamma = (const float*)d_in[6];
    const float* beta  = (const float*)d_in[7];
    float* out = (float*)d_out;

    half_t *xn, *q, *k, *v, *ao, *wgt;
    cudaGetSymbolAddress((void**)&xn, g_xn);
    cudaGetSymbolAddress((void**)&q,  g_q);
    cudaGetSymbolAddress((void**)&k,  g_k);
    cudaGetSymbolAddress((void**)&v,  g_v);
    cudaGetSymbolAddress((void**)&ao, g_ao);
    cudaGetSymbolAddress((void**)&wgt, g_w);

    // 0. convert weights to fp16
    const int CB = WSZ / 4 / 256;
    cvt_arr<<<CB, 256>>>(Wq, wgt + 0*WSZ);
    cvt_arr<<<CB, 256>>>(Wk, wgt + 1*WSZ);
    cvt_arr<<<CB, 256>>>(Wv, wgt + 2*WSZ);
    cvt_arr<<<CB, 256>>>(Wo, wgt + 3*WSZ);

    // 1. LayerNorm -> fp16
    ln_kernel<<<MROWS, 256>>>(x, gamma, beta, xn);

    // 2. Fused QKV projections
    dim3 ggrid(HDIM / 128, MROWS / 128, 3);
    gemm_hf<0><<<ggrid, 256>>>(xn, wgt, q, k, v, nullptr, nullptr, nullptr);

    // 3. Flash attention
    dim3 agrid(SEQ / 128, BATCH * NH);
    attn_hf<<<agrid, 256>>>(q, k, v, ao);

    // 4. Output projection + bias + residual (fp32 out)
    dim3 ogrid(HDIM / 128, MROWS / 128, 1);
    gemm_hf<1><<<ogrid, 256>>>(ao, wgt + 3*WSZ, nullptr, nullptr, nullptr,
                               out, bo, x);
}

// round 16
// speedup vs baseline: 7.2028x; 1.6568x over previous
#include <cuda_runtime.h>
#include <cuda_fp16.h>
#include <math.h>
#include <stdint.h>

#define HDIM 1024
#define NH 16
#define HD 64
#define BATCH 2
#define SEQ 2048
#define MROWS (BATCH*SEQ)   // 4096
#define LN_EPS 1e-5f
#define WSZ (HDIM*HDIM)

typedef __half half_t;

// ---------------- scratch (allocation-free rule: __device__ globals) --------
__device__ half_t g_xn[MROWS*HDIM];
__device__ half_t g_q [MROWS*HDIM];
__device__ half_t g_k [MROWS*HDIM];
__device__ half_t g_v [MROWS*HDIM];
__device__ half_t g_ao[MROWS*HDIM];
__device__ half_t g_w [4*WSZ];

// ---------------- helpers ---------------------------------------------------
__device__ __forceinline__ uint32_t pack2h(float a, float b) {
    __half2 t = __floats2half2_rn(a, b);
    return *reinterpret_cast<uint32_t*>(&t);
}
__device__ __forceinline__ void mma16(float* d, const uint32_t* a, uint32_t b0, uint32_t b1) {
    asm volatile(
        "mma.sync.aligned.m16n8k16.row.col.f32.f16.f16.f32 "
        "{%0,%1,%2,%3},{%4,%5,%6,%7},{%8,%9},{%0,%1,%2,%3};"
        : "+f"(d[0]), "+f"(d[1]), "+f"(d[2]), "+f"(d[3])
        : "r"(a[0]), "r"(a[1]), "r"(a[2]), "r"(a[3]), "r"(b0), "r"(b1));
}
__device__ __forceinline__ uint32_t smem_u32(const void* p) {
    return (uint32_t)__cvta_generic_to_shared(p);
}
__device__ __forceinline__ void cpa16(uint32_t s, const void* g) {
    asm volatile("cp.async.cg.shared.global [%0], [%1], 16;" :: "r"(s), "l"(g));
}
__device__ __forceinline__ void ldsm_x4(uint32_t* r, uint32_t addr) {
    asm volatile("ldmatrix.sync.aligned.m8n8.x4.shared.b16 {%0,%1,%2,%3},[%4];"
                 : "=r"(r[0]), "=r"(r[1]), "=r"(r[2]), "=r"(r[3]) : "r"(addr));
}
__device__ __forceinline__ void ldsm_x4_t(uint32_t* r, uint32_t addr) {
    asm volatile("ldmatrix.sync.aligned.m8n8.x4.trans.shared.b16 {%0,%1,%2,%3},[%4];"
                 : "=r"(r[0]), "=r"(r[1]), "=r"(r[2]), "=r"(r[3]) : "r"(addr));
}
#define CP_COMMIT asm volatile("cp.async.commit_group;")
#define CP_WAIT0  asm volatile("cp.async.wait_group 0;")
#define CP_WAIT1  asm volatile("cp.async.wait_group 1;")

// ---------------- weight convert: fp32 -> fp16 (all 4 mats, one launch) -----
__global__ void cvt_all(const float* __restrict__ s0, const float* __restrict__ s1,
                        const float* __restrict__ s2, const float* __restrict__ s3,
                        half_t* __restrict__ dst)
{
    int gi = blockIdx.x * 256 + threadIdx.x;      // 0 .. 4*WSZ/4-1
    int mat = gi >> 18;                            // WSZ/4 = 262144 per matrix
    int i   = gi & 0x3FFFF;
    const float* src = (mat == 0) ? s0 : (mat == 1) ? s1 : (mat == 2) ? s2 : s3;
    float4 v = ((const float4*)src)[i];
    uint32_t* d = (uint32_t*)(dst + (size_t)mat * WSZ);
    d[2*i]   = pack2h(v.x, v.y);
    d[2*i+1] = pack2h(v.z, v.w);
}

// ---------------- LayerNorm -> fp16 ------------------------------------------
__global__ void ln_kernel(const float* __restrict__ x,
                          const float* __restrict__ gamma,
                          const float* __restrict__ beta,
                          half_t* __restrict__ xn)
{
    int row = blockIdx.x;
    int tid = threadIdx.x;
    const float4* xr = (const float4*)(x + (size_t)row * HDIM);
    float4 v = xr[tid];
    float s  = v.x + v.y + v.z + v.w;
    float ss = v.x*v.x + v.y*v.y + v.z*v.z + v.w*v.w;
    #pragma unroll
    for (int o = 16; o; o >>= 1) {
        s  += __shfl_xor_sync(0xffffffffu, s,  o);
        ss += __shfl_xor_sync(0xffffffffu, ss, o);
    }
    __shared__ float red0[8], red1[8];
    int w = tid >> 5, l = tid & 31;
    if (l == 0) { red0[w] = s; red1[w] = ss; }
    __syncthreads();
    float ts = 0.f, tss = 0.f;
    #pragma unroll
    for (int i = 0; i < 8; i++) { ts += red0[i]; tss += red1[i]; }
    float mu  = ts * (1.0f / HDIM);
    float var = tss * (1.0f / HDIM) - mu * mu;
    float inv = rsqrtf(var + LN_EPS);

    float4 g = ((const float4*)gamma)[tid];
    float4 b = ((const float4*)beta)[tid];
    float o0 = (v.x - mu) * inv * g.x + b.x;
    float o1 = (v.y - mu) * inv * g.y + b.y;
    float o2 = (v.z - mu) * inv * g.z + b.z;
    float o3 = (v.w - mu) * inv * g.w + b.w;
    uint32_t base = row * (HDIM/2) + tid * 2;
    ((uint32_t*)xn)[base]   = pack2h(o0, o1);
    ((uint32_t*)xn)[base+1] = pack2h(o2, o3);
}

// ---------------- fp16 NT GEMM, 3-stage cp.async ring, 1 sync/iter ----------
// C[M,N] = A[M,K] * W[N,K]^T.  BM=BN=128, BK=32, 256 thr (8 warps 2x4), warp
// tile 64x32.  FINAL=0: fp16 C (z selects W,C); FINAL=1: fp32 C=acc+bias+resid.
#define G_SA 40                       // padded row stride (halfs)
#define G_ARR (128*G_SA)              // halfs per array per stage (5120)
#define G_STGB (2*G_ARR*2)            // stage bytes: A+B = 20480
#define G_SMEM (3*G_STGB)             // 61440 B

template <int FINAL>
__global__ void __launch_bounds__(256, 2)
gemm_hf(const half_t* __restrict__ A, const half_t* __restrict__ W0,
        half_t* C0, half_t* C1, half_t* C2,
        float* __restrict__ Cf, const float* __restrict__ bias,
        const float* __restrict__ resid)
{
    extern __shared__ half_t smg[];

    int z = blockIdx.z;
    const half_t* W = W0 + (size_t)z * WSZ;
    half_t* C = (z == 0) ? C0 : (z == 1 ? C1 : C2);

    int tid  = threadIdx.x;
    int m0   = blockIdx.y * 128;
    int n0   = blockIdx.x * 128;
    int w    = tid >> 5, lane = tid & 31;
    int gid  = lane >> 2, tig = lane & 3;
    int wr   = w >> 2, wc = w & 3;

    float acc[4][4][4];
    #pragma unroll
    for (int i = 0; i < 4; i++)
        #pragma unroll
        for (int j = 0; j < 4; j++)
            #pragma unroll
            for (int e = 0; e < 4; e++) acc[i][j][e] = 0.f;

    int rowA = (lane & 7) + ((lane >> 3) & 1) * 8;
    int colA = ((lane >> 4) & 1) * 8;
    int rowB = (lane & 7) + ((lane >> 4) & 1) * 8;
    int colB = ((lane >> 3) & 1) * 8;

    uint32_t offA[4], offB[2];
    #pragma unroll
    for (int mf = 0; mf < 4; mf++)
        offA[mf] = ((wr*64 + mf*16 + rowA) * G_SA + colA) * 2;
    #pragma unroll
    for (int p = 0; p < 2; p++)
        offB[p] = ((wc*32 + p*16 + rowB) * G_SA + colB) * 2;

    uint32_t smbase = smem_u32(smg);

    auto issue = [&](int s, int k0) {
        uint32_t sb = smbase + (uint32_t)(s % 3) * G_STGB;
        #pragma unroll
        for (int i = 0; i < 2; i++) {
            int ch  = tid * 2 + i;            // 0..511
            int row = ch >> 2, off = (ch & 3) * 8;
            cpa16(sb + (uint32_t)(row*G_SA + off)*2,
                  A + (size_t)(m0 + row) * HDIM + k0 + off);
            cpa16(sb + (uint32_t)G_ARR*2 + (uint32_t)(row*G_SA + off)*2,
                  W + (size_t)(n0 + row) * HDIM + k0 + off);
        }
        CP_COMMIT;
    };

    const int NC = HDIM / 32;                 // 32 chunks
    issue(0, 0);
    issue(1, 32);
    for (int c = 0; c < NC; c++) {
        if (c < NC - 1) { CP_WAIT1; } else { CP_WAIT0; }
        __syncthreads();
        if (c + 2 < NC) issue(c + 2, (c + 2) * 32);

        uint32_t bufA = smbase + (uint32_t)(c % 3) * G_STGB;
        uint32_t bufB = bufA + (uint32_t)G_ARR*2;

        #pragma unroll
        for (int kg = 0; kg < 2; kg++) {
            uint32_t kgo = kg * 32;           // 16 halfs
            uint32_t bb[2][4];
            #pragma unroll
            for (int p = 0; p < 2; p++)
                ldsm_x4(bb[p], bufB + offB[p] + kgo);
            #pragma unroll
            for (int mf = 0; mf < 4; mf++) {
                uint32_t a4[4];
                ldsm_x4(a4, bufA + offA[mf] + kgo);
                #pragma unroll
                for (int p = 0; p < 2; p++) {
                    mma16(acc[mf][2*p],   a4, bb[p][0], bb[p][1]);
                    mma16(acc[mf][2*p+1], a4, bb[p][2], bb[p][3]);
                }
            }
        }
    }

    #pragma unroll
    for (int mf = 0; mf < 4; mf++) {
        int r0 = m0 + wr*64 + mf*16 + gid;
        #pragma unroll
        for (int nf = 0; nf < 4; nf++) {
            int col = n0 + wc*32 + nf*8 + 2*tig;
            if (FINAL) {
                float2 bi = *(const float2*)(bias + col);
                float2 rA = *(const float2*)(resid + (size_t)r0 * HDIM + col);
                float2 rB = *(const float2*)(resid + (size_t)(r0+8) * HDIM + col);
                *(float2*)(Cf + (size_t)r0 * HDIM + col) =
                    make_float2(acc[mf][nf][0] + bi.x + rA.x, acc[mf][nf][1] + bi.y + rA.y);
                *(float2*)(Cf + (size_t)(r0+8) * HDIM + col) =
                    make_float2(acc[mf][nf][2] + bi.x + rB.x, acc[mf][nf][3] + bi.y + rB.y);
            } else {
                ((uint32_t*)C)[((size_t)r0 * HDIM + col) >> 1] =
                    pack2h(acc[mf][nf][0], acc[mf][nf][1]);
                ((uint32_t*)C)[((size_t)(r0+8) * HDIM + col) >> 1] =
                    pack2h(acc[mf][nf][2], acc[mf][nf][3]);
            }
        }
    }
}

// ---------------- flash attention, fp16, 3-stage ring, exp2 softmax ----------
#define ATT_S 72
#define ATT_ARR (64*ATT_S)            // halfs per array (K or V) per stage
#define ATT_STGB (2*ATT_ARR*2)        // stage bytes (K+V) = 36864
#define ATT_SMEM (3*ATT_STGB)         // 55296 B

__global__ void __launch_bounds__(256)
attn_hf(const half_t* __restrict__ q, const half_t* __restrict__ k,
        const half_t* __restrict__ v, half_t* __restrict__ ao)
{
    extern __shared__ half_t sma[];

    int tid = threadIdx.x, w = tid >> 5, lane = tid & 31;
    int gid = lane >> 2, tig = lane & 3;
    int bh = blockIdx.y, b = bh >> 4, h = bh & 15;
    int q0 = blockIdx.x * 128;

    size_t rowg = (size_t)b * SEQ + q0 + w*16 + gid;

    uint32_t qf[4][4];
    #pragma unroll
    for (int kg = 0; kg < 4; kg++) {
        int cb = h*64 + kg*16 + 2*tig;
        size_t i00 = rowg * HDIM + cb;
        size_t i10 = (rowg + 8) * HDIM + cb;
        qf[kg][0] = *(const uint32_t*)&q[i00];
        qf[kg][1] = *(const uint32_t*)&q[i10];
        qf[kg][2] = *(const uint32_t*)&q[i00 + 8];
        qf[kg][3] = *(const uint32_t*)&q[i10 + 8];
    }

    int rowK = (lane & 7) + ((lane >> 4) & 1) * 8;
    int colK = ((lane >> 3) & 1) * 8;
    uint32_t loffK = (rowK * ATT_S + colK) * 2;
    int rowV = (lane & 7) + ((lane >> 3) & 1) * 8;
    int colV = ((lane >> 4) & 1) * 8;
    uint32_t loffV = (rowV * ATT_S + colV) * 2;

    float o[8][4];
    #pragma unroll
    for (int nf = 0; nf < 8; nf++)
        #pragma unroll
        for (int e = 0; e < 4; e++) o[nf][e] = 0.f;
    float mA = -1e30f, mB = -1e30f, lA = 0.f, lB = 0.f;

    uint32_t smbase = smem_u32(sma);
    const half_t* srcs[2] = { k, v };
    auto load_tile = [&](int t) {
        uint32_t sb = smbase + (uint32_t)(t % 3) * ATT_STGB;
        #pragma unroll
        for (int i = 0; i < 4; i++) {
            int ch  = i * 256 + tid;          // 0..1023
            int arr = ch >> 9;
            int r   = (ch >> 3) & 63;
            int c8  = (ch & 7) * 8;
            const half_t* src = srcs[arr] +
                ((size_t)b * SEQ + t*64 + r) * HDIM + h*64 + c8;
            cpa16(sb + (uint32_t)(arr*ATT_ARR + r*ATT_S + c8)*2, src);
        }
        CP_COMMIT;
    };

    // scale folds 1/sqrt(HD) and log2(e): softmax uses exp2 throughout
    const float SC = 0.125f * 1.4426950408889634f;

    const int NT = SEQ / 64;
    load_tile(0);
    load_tile(1);
    for (int t = 0; t < NT; t++) {
        if (t < NT - 1) { CP_WAIT1; } else { CP_WAIT0; }
        __syncthreads();
        if (t + 2 < NT) load_tile(t + 2);

        uint32_t Kb = smbase + (uint32_t)(t % 3) * ATT_STGB;
        uint32_t Vb = Kb + ATT_ARR*2;

        float s[8][4];
        #pragma unroll
        for (int nf = 0; nf < 8; nf++)
            #pragma unroll
            for (int e = 0; e < 4; e++) s[nf][e] = 0.f;

        #pragma unroll
        for (int kg = 0; kg < 4; kg++) {
            #pragma unroll
            for (int p = 0; p < 4; p++) {
                uint32_t koff = (uint32_t)((p*16*ATT_S + kg*16) * 2) + loffK;
                uint32_t k4[4];
                ldsm_x4(k4, Kb + koff);
                mma16(s[2*p],   qf[kg], k4[0], k4[1]);
                mma16(s[2*p+1], qf[kg], k4[2], k4[3]);
            }
        }

        #pragma unroll
        for (int nf = 0; nf < 8; nf++)
            #pragma unroll
            for (int e = 0; e < 4; e++) s[nf][e] *= SC;

        float mxA = -1e30f, mxB = -1e30f;
        #pragma unroll
        for (int nf = 0; nf < 8; nf++) {
            mxA = fmaxf(mxA, fmaxf(s[nf][0], s[nf][1]));
            mxB = fmaxf(mxB, fmaxf(s[nf][2], s[nf][3]));
        }
        #pragma unroll
        for (int ofs = 1; ofs <= 2; ofs <<= 1) {
            mxA = fmaxf(mxA, __shfl_xor_sync(0xffffffffu, mxA, ofs));
            mxB = fmaxf(mxB, __shfl_xor_sync(0xffffffffu, mxB, ofs));
        }
        float mnA = fmaxf(mA, mxA), mnB = fmaxf(mB, mxB);
        float alpA = exp2f(mA - mnA), alpB = exp2f(mB - mnB);
        mA = mnA; mB = mnB;

        float rsA = 0.f, rsB = 0.f;
        #pragma unroll
        for (int nf = 0; nf < 8; nf++) {
            s[nf][0] = exp2f(s[nf][0] - mnA);
            s[nf][1] = exp2f(s[nf][1] - mnA);
            s[nf][2] = exp2f(s[nf][2] - mnB);
            s[nf][3] = exp2f(s[nf][3] - mnB);
            rsA += s[nf][0] + s[nf][1];
            rsB += s[nf][2] + s[nf][3];
        }
        #pragma unroll
        for (int ofs = 1; ofs <= 2; ofs <<= 1) {
            rsA += __shfl_xor_sync(0xffffffffu, rsA, ofs);
            rsB += __shfl_xor_sync(0xffffffffu, rsB, ofs);
        }
        lA = lA * alpA + rsA;
        lB = lB * alpB + rsB;
        #pragma unroll
        for (int nf = 0; nf < 8; nf++) {
            o[nf][0] *= alpA; o[nf][1] *= alpA;
            o[nf][2] *= alpB; o[nf][3] *= alpB;
        }

        #pragma unroll
        for (int kg = 0; kg < 4; kg++) {
            uint32_t aP[4];
            aP[0] = pack2h(s[2*kg][0],   s[2*kg][1]);
            aP[1] = pack2h(s[2*kg][2],   s[2*kg][3]);
            aP[2] = pack2h(s[2*kg+1][0], s[2*kg+1][1]);
            aP[3] = pack2h(s[2*kg+1][2], s[2*kg+1][3]);
            #pragma unroll
            for (int p = 0; p < 4; p++) {
                uint32_t voff = (uint32_t)((kg*16*ATT_S + p*16) * 2) + loffV;
                uint32_t v4[4];
                ldsm_x4_t(v4, Vb + voff);
                mma16(o[2*p],   aP, v4[0], v4[1]);
                mma16(o[2*p+1], aP, v4[2], v4[3]);
            }
        }
    }

    float iA = 1.0f / lA, iB = 1.0f / lB;
    #pragma unroll
    for (int nf = 0; nf < 8; nf++) {
        int col = h*64 + nf*8 + 2*tig;
        ((uint32_t*)ao)[(rowg * HDIM + col) >> 1] =
            pack2h(o[nf][0]*iA, o[nf][1]*iA);
        ((uint32_t*)ao)[((rowg + 8) * HDIM + col) >> 1] =
            pack2h(o[nf][2]*iB, o[nf][3]*iB);
    }
}

// ---------------------------------------------------------------------------
extern "C" void kernel_launch(void* const* d_in, const int* in_sizes, int n_in,
                              void* d_out, int out_size)
{
    const float* x     = (const float*)d_in[0];
    const float* Wq    = (const float*)d_in[1];
    const float* Wk    = (const float*)d_in[2];
    const float* Wv    = (const float*)d_in[3];
    const float* Wo    = (const float*)d_in[4];
    const float* bo    = (const float*)d_in[5];
    const float* gamma = (const float*)d_in[6];
    const float* beta  = (const float*)d_in[7];
    float* out = (float*)d_out;

    half_t *xn, *q, *k, *v, *ao, *wgt;
    cudaGetSymbolAddress((void**)&xn, g_xn);
    cudaGetSymbolAddress((void**)&q,  g_q);
    cudaGetSymbolAddress((void**)&k,  g_k);
    cudaGetSymbolAddress((void**)&v,  g_v);
    cudaGetSymbolAddress((void**)&ao, g_ao);
    cudaGetSymbolAddress((void**)&wgt, g_w);

    cudaFuncSetAttribute(gemm_hf<0>, cudaFuncAttributeMaxDynamicSharedMemorySize, G_SMEM);
    cudaFuncSetAttribute(gemm_hf<1>, cudaFuncAttributeMaxDynamicSharedMemorySize, G_SMEM);
    cudaFuncSetAttribute(attn_hf, cudaFuncAttributeMaxDynamicSharedMemorySize, ATT_SMEM);

    // 0. convert all weights to fp16 (single launch)
    cvt_all<<<4*WSZ/4/256, 256>>>(Wq, Wk, Wv, Wo, wgt);

    // 1. LayerNorm -> fp16
    ln_kernel<<<MROWS, 256>>>(x, gamma, beta, xn);

    // 2. Fused QKV projections
    dim3 ggrid(HDIM / 128, MROWS / 128, 3);
    gemm_hf<0><<<ggrid, 256, G_SMEM>>>(xn, wgt, q, k, v, nullptr, nullptr, nullptr);

    // 3. Flash attention
    dim3 agrid(SEQ / 128, BATCH * NH);
    attn_hf<<<agrid, 256, ATT_SMEM>>>(q, k, v, ao);

    // 4. Output projection + bias + residual (fp32 out)
    dim3 ogrid(HDIM / 128, MROWS / 128, 1);
    gemm_hf<1><<<ogrid, 256, G_SMEM>>>(ao, wgt + 3*WSZ, nullptr, nullptr, nullptr,
                                       out, bo, x);
}